// round 5
// baseline (speedup 1.0000x reference)
#include <cuda_runtime.h>
#include <cuda_bf16.h>
#include <cstdint>

#define DIM 128
#define WT_STRIDE 132   // padded row stride for transposed W
#define MAXV 100000

// Scratch (device globals; no allocation allowed)
__device__ float g_h[MAXV * DIM];      // dinv[v] * (emb @ W)[v]
__device__ float g_nodes[MAXV * DIM];  // aggregated output (pre-bias)
__device__ float g_deg[MAXV];
__device__ float g_dinv[MAXV];
__device__ float g_wt[DIM * WT_STRIDE]; // g_wt[c*132 + k] = W[k][c]

// ---------------------------------------------------------------------------
// packed f32x2 helpers
// ---------------------------------------------------------------------------
__device__ __forceinline__ unsigned long long ffma2(unsigned long long a,
                                                    unsigned long long b,
                                                    unsigned long long c) {
    unsigned long long d;
    asm("fma.rn.f32x2 %0, %1, %2, %3;" : "=l"(d) : "l"(a), "l"(b), "l"(c));
    return d;
}
__device__ __forceinline__ float hadd2(unsigned long long p) {
    float lo, hi;
    asm("mov.b64 {%0, %1}, %2;" : "=f"(lo), "=f"(hi) : "l"(p));
    return lo + hi;
}

// ---------------------------------------------------------------------------
// prep: deg=1 (self-loop) + transpose W into padded g_wt (fused)
// ---------------------------------------------------------------------------
__global__ void k_prep(const float* __restrict__ W, int V) {
    int gid = blockIdx.x * blockDim.x + threadIdx.x;
    if (gid < V) g_deg[gid] = 1.0f;
    if (gid < DIM * DIM) {
        int k = gid >> 7;
        int c = gid & 127;
        g_wt[c * WT_STRIDE + k] = W[gid];
    }
}

__global__ void k_deg(const int* __restrict__ edge, int E) {
    int e = blockIdx.x * blockDim.x + threadIdx.x;
    if (e < E) atomicAdd(&g_deg[edge[E + e]], 1.0f);  // dst = edge_index[1]
}

__global__ void k_dinv(int V) {
    int v = blockIdx.x * blockDim.x + threadIdx.x;
    if (v < V) g_dinv[v] = rsqrtf(g_deg[v]);
}

// ---------------------------------------------------------------------------
// GEMM: g_h = dinv * (X @ W), g_nodes = dinv^2 * (X @ W)   (selfloop fused)
// Column-split for occupancy: gridDim.y=2 selects a 64-col half of W.
// Block = 256 threads; block tile 64 rows x 64 cols.
// Thread tile: 8 rows (rg*8..+7, warp-uniform -> broadcast LDS) x 2 cols
// (cg, cg+32; lane stride 132 words == 4 mod 32 -> conflict-free LDS.128).
// smem = 64*132*4 + 64*128*4 = 65KB -> 3 blocks/SM (24 warps).
// ---------------------------------------------------------------------------
__global__ void __launch_bounds__(256) k_gemm(const float* __restrict__ X, int V) {
    extern __shared__ float sh[];
    float* w_sh = sh;                         // [64][132]   (this col-half)
    float* x_sh = sh + 64 * WT_STRIDE;        // [64][128]

    const int tid  = threadIdx.x;
    const int row0 = blockIdx.x * 64;
    const int col0 = blockIdx.y * 64;

    // load W half: 64 rows of wT (cols col0..col0+63): 64*33 float4 = 2112
    {
        const float4* src = reinterpret_cast<const float4*>(g_wt + col0 * WT_STRIDE);
        float4* dst = reinterpret_cast<float4*>(w_sh);
        const int total = 64 * (WT_STRIDE / 4);  // 2112
#pragma unroll
        for (int i = 0; i < 9; i++) {
            int idx = tid + i * 256;
            if (idx < total) dst[idx] = src[idx];
        }
    }
    // load X tile: 64 rows x 32 float4 = 2048; 8 per thread (row-guarded)
    {
        const float4* X4 = reinterpret_cast<const float4*>(X) + (size_t)row0 * 32;
        float4* x4 = reinterpret_cast<float4*>(x_sh);
#pragma unroll
        for (int i = 0; i < 8; i++) {
            int idx = tid + i * 256;
            int r = idx >> 5;
            float4 v = make_float4(0.f, 0.f, 0.f, 0.f);
            if (row0 + r < V) v = X4[idx];
            x4[idx] = v;
        }
    }
    __syncthreads();

    const int cg = tid & 31;   // local cols: cg, cg+32
    const int rg = tid >> 5;   // rows: rg*8 .. rg*8+7  (8 row-groups)

    unsigned long long acc[8][2];
#pragma unroll
    for (int r = 0; r < 8; r++) { acc[r][0] = 0ull; acc[r][1] = 0ull; }

    const float* xb = x_sh + (rg * 8) * DIM;
    const float* wb = w_sh + cg * WT_STRIDE;

#pragma unroll 4
    for (int kk = 0; kk < DIM; kk += 4) {
        const ulonglong2 wv0 =
            *reinterpret_cast<const ulonglong2*>(wb + kk);
        const ulonglong2 wv1 =
            *reinterpret_cast<const ulonglong2*>(wb + 32 * WT_STRIDE + kk);
#pragma unroll
        for (int r = 0; r < 8; r++) {
            const ulonglong2 xv =
                *reinterpret_cast<const ulonglong2*>(xb + r * DIM + kk);  // broadcast
            acc[r][0] = ffma2(xv.x, wv0.x, acc[r][0]);
            acc[r][0] = ffma2(xv.y, wv0.y, acc[r][0]);
            acc[r][1] = ffma2(xv.x, wv1.x, acc[r][1]);
            acc[r][1] = ffma2(xv.y, wv1.y, acc[r][1]);
        }
    }

#pragma unroll
    for (int r = 0; r < 8; r++) {
        int row = row0 + rg * 8 + r;
        if (row < V) {
            float s  = g_dinv[row];
            float s2 = s * s;
            size_t base = (size_t)row * DIM + col0 + cg;
#pragma unroll
            for (int c = 0; c < 2; c++) {
                float v = hadd2(acc[r][c]);
                g_h[base + c * 32]     = v * s;   // coalesced per warp
                g_nodes[base + c * 32] = v * s2;
            }
        }
    }
}

// ---------------------------------------------------------------------------
// edge aggregation: one warp per edge; g_h already carries dinv[src].
// ---------------------------------------------------------------------------
__global__ void __launch_bounds__(256) k_edge_agg(const int* __restrict__ edge, int E) {
    int warp = (blockIdx.x * blockDim.x + threadIdx.x) >> 5;
    int lane = threadIdx.x & 31;
    if (warp >= E) return;
    int src = __ldg(edge + warp);       // edge_index[0]
    int dst = __ldg(edge + E + warp);   // edge_index[1]
    float norm = __ldg(g_dinv + dst);   // dinv[src] already folded into g_h
    const float4 v = reinterpret_cast<const float4*>(g_h)[(size_t)src * 32 + lane];
    float* p = g_nodes + (size_t)dst * DIM + lane * 4;
    asm volatile("red.global.add.v4.f32 [%0], {%1, %2, %3, %4};"
                 :: "l"(p), "f"(v.x * norm), "f"(v.y * norm),
                    "f"(v.z * norm), "f"(v.w * norm)
                 : "memory");
}

// ---------------------------------------------------------------------------
// scoring: block = one item; 4 warps x 16 samples; bias folded in.
// Warp-per-sample: each LDG.128 covers one contiguous 512B row (coalesced).
// ---------------------------------------------------------------------------
__global__ void __launch_bounds__(128) k_scores(const int* __restrict__ items,
                                                const int* __restrict__ samples,
                                                const float* __restrict__ bias,
                                                float* __restrict__ out, int S) {
    __shared__ float item_sh[DIM];
    __shared__ float bias_sh[DIM];
    const int b = blockIdx.x;
    const int t = threadIdx.x;

    const int item = __ldg(items + b);
    {
        float bv = __ldg(bias + t);
        bias_sh[t] = bv;
        item_sh[t] = g_nodes[(size_t)item * DIM + t] + bv;
    }
    __syncthreads();

    const int warp = t >> 5;
    const int lane = t & 31;
    const float4 iv = reinterpret_cast<const float4*>(item_sh)[lane];
    const float4 bv = reinterpret_cast<const float4*>(bias_sh)[lane];

    const int* samp = samples + (size_t)b * S;
#pragma unroll 4
    for (int i = 0; i < 16; i++) {
        int s = warp * 16 + i;
        int sidx = __ldg(samp + s);
        const float4 sv = reinterpret_cast<const float4*>(g_nodes)[(size_t)sidx * 32 + lane];
        float p = iv.x * (sv.x + bv.x) + iv.y * (sv.y + bv.y) +
                  iv.z * (sv.z + bv.z) + iv.w * (sv.w + bv.w);
#pragma unroll
        for (int off = 16; off > 0; off >>= 1)
            p += __shfl_xor_sync(0xffffffffu, p, off);
        if (lane == 0) out[(size_t)b * S + s] = p;
    }
}

// ---------------------------------------------------------------------------
// launcher
// ---------------------------------------------------------------------------
extern "C" void kernel_launch(void* const* d_in, const int* in_sizes, int n_in,
                              void* d_out, int out_size) {
    const int*   items   = (const int*)d_in[0];
    const int*   samples = (const int*)d_in[1];
    const int*   edge    = (const int*)d_in[2];
    const float* emb     = (const float*)d_in[3];
    const float* W       = (const float*)d_in[4];
    const float* bias    = (const float*)d_in[5];
    float*       out     = (float*)d_out;

    const int B = in_sizes[0];
    const int S = in_sizes[1] / B;
    const int E = in_sizes[2] / 2;
    const int V = in_sizes[3] / DIM;

    // prep (deg=1 + W transpose), degrees
    k_prep<<<(V + 255) / 256, 256>>>(W, V);
    k_deg<<<(E + 255) / 256, 256>>>(edge, E);
    k_dinv<<<(V + 255) / 256, 256>>>(V);

    // GEMM + fused self-loop/scaling, column-split (65KB smem -> 3 blocks/SM)
    const int gemm_smem = (64 * WT_STRIDE + 64 * DIM) * (int)sizeof(float); // 66560
    cudaFuncSetAttribute(k_gemm, cudaFuncAttributeMaxDynamicSharedMemorySize, gemm_smem);
    dim3 ggrid((V + 63) / 64, 2);
    k_gemm<<<ggrid, 256, gemm_smem>>>(emb, V);

    // edge scatter-add
    k_edge_agg<<<(E + 7) / 8, 256>>>(edge, E);

    // scoring with folded bias
    k_scores<<<B, 128>>>(items, samples, bias, out, S);
}

// round 7
// speedup vs baseline: 1.1441x; 1.1441x over previous
#include <cuda_runtime.h>
#include <cuda_bf16.h>
#include <cstdint>

#define DIM 128
#define TILE_M 128
#define MAXV 100000
#define SH 136            // padded smem row stride in bf16 halves (272B)

// ---------------------------------------------------------------------------
// Device globals (no allocation allowed)
// ---------------------------------------------------------------------------
__device__ float g_h[MAXV * DIM];      // dinv[v] * (emb @ W)[v]
__device__ float g_nodes[MAXV * DIM];  // dinv^2 * h, then scatter-add target
__device__ float g_deg[MAXV];
__device__ float g_dinv[MAXV];
// W transposed + bf16-split: g_w1[n*128+k] = bf16_hi(W[k][n]), g_w2 = residual
__device__ __align__(16) __nv_bfloat16 g_w1[DIM * DIM];
__device__ __align__(16) __nv_bfloat16 g_w2[DIM * DIM];

// ---------------------------------------------------------------------------
// mma.sync bf16 m16n8k16 (row.col, f32 accum) — supported on base sm_100
// ---------------------------------------------------------------------------
#define MMA_BF16(c, a, b0, b1)                                              \
    asm volatile(                                                           \
        "mma.sync.aligned.m16n8k16.row.col.f32.bf16.bf16.f32 "              \
        "{%0,%1,%2,%3}, {%4,%5,%6,%7}, {%8,%9}, {%0,%1,%2,%3};"             \
        : "+f"((c)[0]), "+f"((c)[1]), "+f"((c)[2]), "+f"((c)[3])            \
        : "r"((a)[0]), "r"((a)[1]), "r"((a)[2]), "r"((a)[3]),               \
          "r"(b0), "r"(b1))

__device__ __forceinline__ uint32_t ld32h(const __nv_bfloat16* p, int off_halves) {
    return *reinterpret_cast<const uint32_t*>(p + off_halves);
}
__device__ __forceinline__ uint32_t pack_bf2(__nv_bfloat16 lo, __nv_bfloat16 hi) {
    __nv_bfloat162 v(lo, hi);  // lo -> low 16 bits (first fragment element)
    return *reinterpret_cast<uint32_t*>(&v);
}

// ---------------------------------------------------------------------------
// prep: deg=1 + transpose/split W into g_w1/g_w2
// ---------------------------------------------------------------------------
__global__ void k_prep(const float* __restrict__ W, int V) {
    int gid = blockIdx.x * blockDim.x + threadIdx.x;
    if (gid < V) g_deg[gid] = 1.0f;
    if (gid < DIM * DIM) {
        int k = gid >> 7;
        int n = gid & 127;
        float x = W[gid];
        __nv_bfloat16 hi = __float2bfloat16(x);
        __nv_bfloat16 lo = __float2bfloat16(x - __bfloat162float(hi));
        g_w1[n * DIM + k] = hi;
        g_w2[n * DIM + k] = lo;
    }
}

__global__ void k_deg(const int* __restrict__ edge, int E) {
    int e = blockIdx.x * blockDim.x + threadIdx.x;
    if (e < E) atomicAdd(&g_deg[edge[E + e]], 1.0f);  // dst = edge_index[1]
}

__global__ void k_dinv(int V) {
    int v = blockIdx.x * blockDim.x + threadIdx.x;
    if (v < V) g_dinv[v] = rsqrtf(g_deg[v]);
}

// ---------------------------------------------------------------------------
// Tensor-core GEMM (mma.sync bf16, 4-pass split => ~fp32 accuracy).
// CTA: 256 thr = 8 warps; tile 128 rows x 128 cols.
// Warp tile: 32 rows x 64 cols = 2 m16-tiles x 8 n-tiles.
// SMEM layout (bytes):
//   x1[128][136]h @0, x2 @34816, w1 @69632, w2 @104448, dinv @139264
//   epilogue stage[128][132]f32 aliases x1+x2 (67584 <= 69632).
// ---------------------------------------------------------------------------
#define X1_OFF 0
#define X2_OFF (DIM * SH * 2)
#define W1_OFF (2 * DIM * SH * 2)
#define W2_OFF (3 * DIM * SH * 2)
#define DINV_OFF (4 * DIM * SH * 2)
#define GEMM_SMEM (DINV_OFF + 512)
#define STAGE_STRIDE 132

__global__ void __launch_bounds__(256) k_gemm(const float* __restrict__ X, int V) {
    extern __shared__ __align__(16) unsigned char smem[];
    __nv_bfloat16* x1 = reinterpret_cast<__nv_bfloat16*>(smem + X1_OFF);
    __nv_bfloat16* x2 = reinterpret_cast<__nv_bfloat16*>(smem + X2_OFF);
    __nv_bfloat16* w1 = reinterpret_cast<__nv_bfloat16*>(smem + W1_OFF);
    __nv_bfloat16* w2 = reinterpret_cast<__nv_bfloat16*>(smem + W2_OFF);
    float* dinv_sh = reinterpret_cast<float*>(smem + DINV_OFF);

    const int tid = threadIdx.x;
    const int wid = tid >> 5;
    const int lane = tid & 31;
    const int row0 = blockIdx.x * TILE_M;

    if (tid < TILE_M) {
        int r = row0 + tid;
        dinv_sh[tid] = (r < V) ? g_dinv[r] : 0.0f;
    }

    // Copy W tiles into padded smem: 128 rows x 16 uint4 each buffer
    {
        const uint4* s1 = reinterpret_cast<const uint4*>(g_w1);
        const uint4* s2 = reinterpret_cast<const uint4*>(g_w2);
#pragma unroll
        for (int i = 0; i < 8; i++) {
            int idx = tid + i * 256;     // 0..2047
            int r = idx >> 4;
            int c = idx & 15;
            reinterpret_cast<uint4*>(w1 + r * SH)[c] = s1[idx];
            reinterpret_cast<uint4*>(w2 + r * SH)[c] = s2[idx];
        }
    }
    // Load + split X: 128 rows x 32 float4 = 4096; 16 per thread
    {
        const float4* X4 = reinterpret_cast<const float4*>(X);
#pragma unroll
        for (int i = 0; i < 16; i++) {
            int idx = tid + i * 256;
            int r = idx >> 5;
            int c4 = idx & 31;           // 4-float chunk
            float4 v = make_float4(0.f, 0.f, 0.f, 0.f);
            if (row0 + r < V) v = X4[(size_t)(row0 + r) * 32 + c4];
            __nv_bfloat16 h0 = __float2bfloat16(v.x);
            __nv_bfloat16 h1 = __float2bfloat16(v.y);
            __nv_bfloat16 h2 = __float2bfloat16(v.z);
            __nv_bfloat16 h3 = __float2bfloat16(v.w);
            __nv_bfloat16 l0 = __float2bfloat16(v.x - __bfloat162float(h0));
            __nv_bfloat16 l1 = __float2bfloat16(v.y - __bfloat162float(h1));
            __nv_bfloat16 l2 = __float2bfloat16(v.z - __bfloat162float(h2));
            __nv_bfloat16 l3 = __float2bfloat16(v.w - __bfloat162float(h3));
            uint2 hp = make_uint2(pack_bf2(h0, h1), pack_bf2(h2, h3));
            uint2 lp = make_uint2(pack_bf2(l0, l1), pack_bf2(l2, l3));
            *reinterpret_cast<uint2*>(x1 + r * SH + c4 * 4) = hp;
            *reinterpret_cast<uint2*>(x2 + r * SH + c4 * 4) = lp;
        }
    }
    __syncthreads();

    // Warp tiling
    const int wr = (wid & 3) * 32;      // warp row base
    const int wc = (wid >> 2) * 64;     // warp col base
    const int g = lane >> 2;            // group 0..7
    const int tg = lane & 3;            // thread-in-group 0..3

    float acc[2][8][4];
#pragma unroll
    for (int mt = 0; mt < 2; mt++)
#pragma unroll
        for (int nt = 0; nt < 8; nt++)
#pragma unroll
            for (int j = 0; j < 4; j++) acc[mt][nt][j] = 0.0f;

#pragma unroll
    for (int kb = 0; kb < DIM; kb += 16) {
        uint32_t ah[2][4], al[2][4];
#pragma unroll
        for (int mt = 0; mt < 2; mt++) {
            int rb = wr + mt * 16;
            int o0 = (rb + g) * SH + kb + 2 * tg;
            int o1 = (rb + g + 8) * SH + kb + 2 * tg;
            ah[mt][0] = ld32h(x1, o0);
            ah[mt][1] = ld32h(x1, o1);
            ah[mt][2] = ld32h(x1, o0 + 8);
            ah[mt][3] = ld32h(x1, o1 + 8);
            al[mt][0] = ld32h(x2, o0);
            al[mt][1] = ld32h(x2, o1);
            al[mt][2] = ld32h(x2, o0 + 8);
            al[mt][3] = ld32h(x2, o1 + 8);
        }
#pragma unroll
        for (int nt = 0; nt < 8; nt++) {
            int nb = (wc + nt * 8 + g) * SH + kb + 2 * tg;
            uint32_t bh0 = ld32h(w1, nb);
            uint32_t bh1 = ld32h(w1, nb + 8);
            uint32_t bl0 = ld32h(w2, nb);
            uint32_t bl1 = ld32h(w2, nb + 8);
#pragma unroll
            for (int mt = 0; mt < 2; mt++) {
                MMA_BF16(acc[mt][nt], ah[mt], bh0, bh1);
                MMA_BF16(acc[mt][nt], ah[mt], bl0, bl1);
                MMA_BF16(acc[mt][nt], al[mt], bh0, bh1);
                MMA_BF16(acc[mt][nt], al[mt], bl0, bl1);
            }
        }
    }
    __syncthreads();   // x1/x2 become the epilogue stage

    // Stage accumulators: stage[m][c], stride 132 floats
    {
        float* stage = reinterpret_cast<float*>(smem);
#pragma unroll
        for (int mt = 0; mt < 2; mt++) {
#pragma unroll
            for (int nt = 0; nt < 8; nt++) {
                int rs = wr + mt * 16 + g;
                int cs = wc + nt * 8 + 2 * tg;
                stage[rs * STAGE_STRIDE + cs]           = acc[mt][nt][0];
                stage[rs * STAGE_STRIDE + cs + 1]       = acc[mt][nt][1];
                stage[(rs + 8) * STAGE_STRIDE + cs]     = acc[mt][nt][2];
                stage[(rs + 8) * STAGE_STRIDE + cs + 1] = acc[mt][nt][3];
            }
        }
    }
    __syncthreads();

    // Coalesced dual store with dinv scaling
    {
        const float* stage = reinterpret_cast<const float*>(smem);
#pragma unroll
        for (int i = 0; i < 16; i++) {
            int idx = tid + i * 256;      // 0..4095 float4s
            int m = idx >> 5;
            int c4 = idx & 31;
            int row = row0 + m;
            if (row < V) {
                const float4 v = *reinterpret_cast<const float4*>(
                    stage + m * STAGE_STRIDE + c4 * 4);
                float s = dinv_sh[m];
                float s2 = s * s;
                size_t off = (size_t)row * 32 + c4;
                reinterpret_cast<float4*>(g_h)[off] =
                    make_float4(v.x * s, v.y * s, v.z * s, v.w * s);
                reinterpret_cast<float4*>(g_nodes)[off] =
                    make_float4(v.x * s2, v.y * s2, v.z * s2, v.w * s2);
            }
        }
    }
}

// ---------------------------------------------------------------------------
// edge aggregation: one warp per edge; g_h already carries dinv[src].
// ---------------------------------------------------------------------------
__global__ void __launch_bounds__(256) k_edge_agg(const int* __restrict__ edge, int E) {
    int warp = (blockIdx.x * blockDim.x + threadIdx.x) >> 5;
    int lane = threadIdx.x & 31;
    if (warp >= E) return;
    int src = __ldg(edge + warp);       // edge_index[0]
    int dst = __ldg(edge + E + warp);   // edge_index[1]
    float norm = __ldg(g_dinv + dst);   // dinv[src] folded into g_h
    const float4 v = reinterpret_cast<const float4*>(g_h)[(size_t)src * 32 + lane];
    float* p = g_nodes + (size_t)dst * DIM + lane * 4;
    asm volatile("red.global.add.v4.f32 [%0], {%1, %2, %3, %4};"
                 :: "l"(p), "f"(v.x * norm), "f"(v.y * norm),
                    "f"(v.z * norm), "f"(v.w * norm)
                 : "memory");
}

// ---------------------------------------------------------------------------
// scoring: block = one item; 4 warps x 16 samples; bias folded in.
// ---------------------------------------------------------------------------
__global__ void __launch_bounds__(128) k_scores(const int* __restrict__ items,
                                                const int* __restrict__ samples,
                                                const float* __restrict__ bias,
                                                float* __restrict__ out, int S) {
    __shared__ float item_sh[DIM];
    __shared__ float bias_sh[DIM];
    const int b = blockIdx.x;
    const int t = threadIdx.x;

    const int item = __ldg(items + b);
    {
        float bv = __ldg(bias + t);
        bias_sh[t] = bv;
        item_sh[t] = g_nodes[(size_t)item * DIM + t] + bv;
    }
    __syncthreads();

    const int warp = t >> 5;
    const int lane = t & 31;
    const float4 iv = reinterpret_cast<const float4*>(item_sh)[lane];
    const float4 bv = reinterpret_cast<const float4*>(bias_sh)[lane];

    const int* samp = samples + (size_t)b * S;
#pragma unroll 4
    for (int i = 0; i < 16; i++) {
        int s = warp * 16 + i;
        int sidx = __ldg(samp + s);
        const float4 sv = reinterpret_cast<const float4*>(g_nodes)[(size_t)sidx * 32 + lane];
        float p = iv.x * (sv.x + bv.x) + iv.y * (sv.y + bv.y) +
                  iv.z * (sv.z + bv.z) + iv.w * (sv.w + bv.w);
#pragma unroll
        for (int off = 16; off > 0; off >>= 1)
            p += __shfl_xor_sync(0xffffffffu, p, off);
        if (lane == 0) out[(size_t)b * S + s] = p;
    }
}

// ---------------------------------------------------------------------------
// launcher
// ---------------------------------------------------------------------------
extern "C" void kernel_launch(void* const* d_in, const int* in_sizes, int n_in,
                              void* d_out, int out_size) {
    const int*   items   = (const int*)d_in[0];
    const int*   samples = (const int*)d_in[1];
    const int*   edge    = (const int*)d_in[2];
    const float* emb     = (const float*)d_in[3];
    const float* W       = (const float*)d_in[4];
    const float* bias    = (const float*)d_in[5];
    float*       out     = (float*)d_out;

    const int B = in_sizes[0];
    const int S = in_sizes[1] / B;
    const int E = in_sizes[2] / 2;
    const int V = in_sizes[3] / DIM;

    // prep (deg=1 + W transpose/split), degrees
    k_prep<<<(V + 255) / 256, 256>>>(W, V);
    k_deg<<<(E + 255) / 256, 256>>>(edge, E);
    k_dinv<<<(V + 255) / 256, 256>>>(V);

    // tensor-core GEMM + fused self-loop/scaling
    cudaFuncSetAttribute(k_gemm, cudaFuncAttributeMaxDynamicSharedMemorySize, GEMM_SMEM);
    k_gemm<<<(V + TILE_M - 1) / TILE_M, 256, GEMM_SMEM>>>(emb, V);

    // edge scatter-add
    k_edge_agg<<<(E + 7) / 8, 256>>>(edge, E);

    // scoring with folded bias
    k_scores<<<B, 128>>>(items, samples, bias, out, S);
}

// round 8
// speedup vs baseline: 1.2059x; 1.0540x over previous
#include <cuda_runtime.h>
#include <cuda_bf16.h>
#include <cstdint>

#define DIM 128
#define TILE_M 64
#define MAXV 100000
#define SH 136            // padded smem row stride in bf16 halves (272B)

// ---------------------------------------------------------------------------
// Device globals (no allocation allowed)
// ---------------------------------------------------------------------------
__device__ float g_h[MAXV * DIM];      // dinv[v] * (emb @ W)[v]
__device__ float g_nodes[MAXV * DIM];  // dinv^2 * h, then scatter-add target
__device__ float g_deg[MAXV];
__device__ float g_dinv[MAXV];
// W transposed + bf16-split: g_w1[n*128+k] = bf16_hi(W[k][n]), g_w2 = residual
__device__ __align__(16) __nv_bfloat16 g_w1[DIM * DIM];
__device__ __align__(16) __nv_bfloat16 g_w2[DIM * DIM];

// ---------------------------------------------------------------------------
// mma.sync bf16 m16n8k16 (row.col, f32 accum) — supported on base sm_100
// ---------------------------------------------------------------------------
#define MMA_BF16(c, a, b0, b1)                                              \
    asm volatile(                                                           \
        "mma.sync.aligned.m16n8k16.row.col.f32.bf16.bf16.f32 "              \
        "{%0,%1,%2,%3}, {%4,%5,%6,%7}, {%8,%9}, {%0,%1,%2,%3};"             \
        : "+f"((c)[0]), "+f"((c)[1]), "+f"((c)[2]), "+f"((c)[3])            \
        : "r"((a)[0]), "r"((a)[1]), "r"((a)[2]), "r"((a)[3]),               \
          "r"(b0), "r"(b1))

__device__ __forceinline__ uint32_t ld32h(const __nv_bfloat16* p, int off_halves) {
    return *reinterpret_cast<const uint32_t*>(p + off_halves);
}
__device__ __forceinline__ uint32_t pack_bf2(__nv_bfloat16 lo, __nv_bfloat16 hi) {
    __nv_bfloat162 v(lo, hi);
    return *reinterpret_cast<uint32_t*>(&v);
}

// ---------------------------------------------------------------------------
// prep: deg=1 + transpose/split W into g_w1/g_w2
// ---------------------------------------------------------------------------
__global__ void k_prep(const float* __restrict__ W, int V) {
    int gid = blockIdx.x * blockDim.x + threadIdx.x;
    if (gid < V) g_deg[gid] = 1.0f;
    if (gid < DIM * DIM) {
        int k = gid >> 7;
        int n = gid & 127;
        float x = W[gid];
        __nv_bfloat16 hi = __float2bfloat16(x);
        __nv_bfloat16 lo = __float2bfloat16(x - __bfloat162float(hi));
        g_w1[n * DIM + k] = hi;
        g_w2[n * DIM + k] = lo;
    }
}

__global__ void k_deg(const int* __restrict__ edge, int E) {
    int e = blockIdx.x * blockDim.x + threadIdx.x;
    if (e < E) atomicAdd(&g_deg[edge[E + e]], 1.0f);  // dst = edge_index[1]
}

__global__ void k_dinv(int V) {
    int v = blockIdx.x * blockDim.x + threadIdx.x;
    if (v < V) g_dinv[v] = rsqrtf(g_deg[v]);
}

// ---------------------------------------------------------------------------
// Tensor-core GEMM (mma.sync bf16, 3-pass split: x1w1 + x1w2 + x2w1).
// CTA: 256 thr = 8 warps; tile 64 rows x 128 cols; 2 CTAs/SM (104.7KB smem).
// Warp tile: 32 rows x 32 cols = 2 m16-tiles x 4 n-tiles.
// SMEM (bytes): x1 @0 (17408), x2 @17408, w1 @34816 (34816), w2 @69632,
//               dinv @104448; epilogue stage[64][132]f32 (33792) aliases x1+x2.
// ---------------------------------------------------------------------------
#define X1_OFF 0
#define X2_OFF (TILE_M * SH * 2)
#define W1_OFF (2 * TILE_M * SH * 2)
#define W2_OFF (W1_OFF + DIM * SH * 2)
#define DINV_OFF (W2_OFF + DIM * SH * 2)
#define GEMM_SMEM (DINV_OFF + 256)
#define STAGE_STRIDE 132

__global__ void __launch_bounds__(256, 2) k_gemm(const float* __restrict__ X, int V) {
    extern __shared__ __align__(16) unsigned char smem[];
    __nv_bfloat16* x1 = reinterpret_cast<__nv_bfloat16*>(smem + X1_OFF);
    __nv_bfloat16* x2 = reinterpret_cast<__nv_bfloat16*>(smem + X2_OFF);
    __nv_bfloat16* w1 = reinterpret_cast<__nv_bfloat16*>(smem + W1_OFF);
    __nv_bfloat16* w2 = reinterpret_cast<__nv_bfloat16*>(smem + W2_OFF);
    float* dinv_sh = reinterpret_cast<float*>(smem + DINV_OFF);

    const int tid = threadIdx.x;
    const int wid = tid >> 5;
    const int lane = tid & 31;
    const int row0 = blockIdx.x * TILE_M;

    if (tid < TILE_M) {
        int r = row0 + tid;
        dinv_sh[tid] = (r < V) ? g_dinv[r] : 0.0f;
    }

    // Copy W tiles into padded smem: 128 rows x 16 uint4 per buffer
    {
        const uint4* s1 = reinterpret_cast<const uint4*>(g_w1);
        const uint4* s2 = reinterpret_cast<const uint4*>(g_w2);
#pragma unroll
        for (int i = 0; i < 8; i++) {
            int idx = tid + i * 256;     // 0..2047
            int r = idx >> 4;
            int c = idx & 15;
            reinterpret_cast<uint4*>(w1 + r * SH)[c] = s1[idx];
            reinterpret_cast<uint4*>(w2 + r * SH)[c] = s2[idx];
        }
    }
    // Load + split X: 64 rows x 32 float4 = 2048; 8 per thread
    {
        const float4* X4 = reinterpret_cast<const float4*>(X);
#pragma unroll
        for (int i = 0; i < 8; i++) {
            int idx = tid + i * 256;
            int r = idx >> 5;
            int c4 = idx & 31;
            float4 v = make_float4(0.f, 0.f, 0.f, 0.f);
            if (row0 + r < V) v = X4[(size_t)(row0 + r) * 32 + c4];
            __nv_bfloat16 h0 = __float2bfloat16(v.x);
            __nv_bfloat16 h1 = __float2bfloat16(v.y);
            __nv_bfloat16 h2 = __float2bfloat16(v.z);
            __nv_bfloat16 h3 = __float2bfloat16(v.w);
            __nv_bfloat16 l0 = __float2bfloat16(v.x - __bfloat162float(h0));
            __nv_bfloat16 l1 = __float2bfloat16(v.y - __bfloat162float(h1));
            __nv_bfloat16 l2 = __float2bfloat16(v.z - __bfloat162float(h2));
            __nv_bfloat16 l3 = __float2bfloat16(v.w - __bfloat162float(h3));
            uint2 hp = make_uint2(pack_bf2(h0, h1), pack_bf2(h2, h3));
            uint2 lp = make_uint2(pack_bf2(l0, l1), pack_bf2(l2, l3));
            *reinterpret_cast<uint2*>(x1 + r * SH + c4 * 4) = hp;
            *reinterpret_cast<uint2*>(x2 + r * SH + c4 * 4) = lp;
        }
    }
    __syncthreads();

    // Warp tiling: 2 row-groups x 4 col-groups of 32x32
    const int wr = (wid & 1) * 32;
    const int wc = (wid >> 1) * 32;
    const int g = lane >> 2;
    const int tg = lane & 3;

    float acc[2][4][4];
#pragma unroll
    for (int mt = 0; mt < 2; mt++)
#pragma unroll
        for (int nt = 0; nt < 4; nt++)
#pragma unroll
            for (int j = 0; j < 4; j++) acc[mt][nt][j] = 0.0f;

#pragma unroll
    for (int kb = 0; kb < DIM; kb += 16) {
        uint32_t ah[2][4], al[2][4];
#pragma unroll
        for (int mt = 0; mt < 2; mt++) {
            int rb = wr + mt * 16;
            int o0 = (rb + g) * SH + kb + 2 * tg;
            int o1 = (rb + g + 8) * SH + kb + 2 * tg;
            ah[mt][0] = ld32h(x1, o0);
            ah[mt][1] = ld32h(x1, o1);
            ah[mt][2] = ld32h(x1, o0 + 8);
            ah[mt][3] = ld32h(x1, o1 + 8);
            al[mt][0] = ld32h(x2, o0);
            al[mt][1] = ld32h(x2, o1);
            al[mt][2] = ld32h(x2, o0 + 8);
            al[mt][3] = ld32h(x2, o1 + 8);
        }
#pragma unroll
        for (int nt = 0; nt < 4; nt++) {
            int nb = (wc + nt * 8 + g) * SH + kb + 2 * tg;
            uint32_t bh0 = ld32h(w1, nb);
            uint32_t bh1 = ld32h(w1, nb + 8);
            uint32_t bl0 = ld32h(w2, nb);
            uint32_t bl1 = ld32h(w2, nb + 8);
#pragma unroll
            for (int mt = 0; mt < 2; mt++) {
                MMA_BF16(acc[mt][nt], ah[mt], bh0, bh1);
                MMA_BF16(acc[mt][nt], ah[mt], bl0, bl1);
                MMA_BF16(acc[mt][nt], al[mt], bh0, bh1);
            }
        }
    }
    __syncthreads();   // x1/x2 become the epilogue stage

    // Stage accumulators: stage[m][c], stride 132 floats
    {
        float* stage = reinterpret_cast<float*>(smem);
#pragma unroll
        for (int mt = 0; mt < 2; mt++) {
#pragma unroll
            for (int nt = 0; nt < 4; nt++) {
                int rs = wr + mt * 16 + g;
                int cs = wc + nt * 8 + 2 * tg;
                stage[rs * STAGE_STRIDE + cs]           = acc[mt][nt][0];
                stage[rs * STAGE_STRIDE + cs + 1]       = acc[mt][nt][1];
                stage[(rs + 8) * STAGE_STRIDE + cs]     = acc[mt][nt][2];
                stage[(rs + 8) * STAGE_STRIDE + cs + 1] = acc[mt][nt][3];
            }
        }
    }
    __syncthreads();

    // Coalesced dual store with dinv scaling: 64 rows x 32 float4 = 2048
    {
        const float* stage = reinterpret_cast<const float*>(smem);
#pragma unroll
        for (int i = 0; i < 8; i++) {
            int idx = tid + i * 256;
            int m = idx >> 5;
            int c4 = idx & 31;
            int row = row0 + m;
            if (row < V) {
                const float4 v = *reinterpret_cast<const float4*>(
                    stage + m * STAGE_STRIDE + c4 * 4);
                float s = dinv_sh[m];
                float s2 = s * s;
                size_t off = (size_t)row * 32 + c4;
                reinterpret_cast<float4*>(g_h)[off] =
                    make_float4(v.x * s, v.y * s, v.z * s, v.w * s);
                reinterpret_cast<float4*>(g_nodes)[off] =
                    make_float4(v.x * s2, v.y * s2, v.z * s2, v.w * s2);
            }
        }
    }
}

// ---------------------------------------------------------------------------
// edge aggregation: one warp per edge; g_h already carries dinv[src].
// ---------------------------------------------------------------------------
__global__ void __launch_bounds__(256) k_edge_agg(const int* __restrict__ edge, int E) {
    int warp = (blockIdx.x * blockDim.x + threadIdx.x) >> 5;
    int lane = threadIdx.x & 31;
    if (warp >= E) return;
    int src = __ldg(edge + warp);       // edge_index[0]
    int dst = __ldg(edge + E + warp);   // edge_index[1]
    float norm = __ldg(g_dinv + dst);   // dinv[src] folded into g_h
    const float4 v = reinterpret_cast<const float4*>(g_h)[(size_t)src * 32 + lane];
    float* p = g_nodes + (size_t)dst * DIM + lane * 4;
    asm volatile("red.global.add.v4.f32 [%0], {%1, %2, %3, %4};"
                 :: "l"(p), "f"(v.x * norm), "f"(v.y * norm),
                    "f"(v.z * norm), "f"(v.w * norm)
                 : "memory");
}

// ---------------------------------------------------------------------------
// scoring: block = one item; 4 warps x 16 samples; bias folded in.
// ---------------------------------------------------------------------------
__global__ void __launch_bounds__(128) k_scores(const int* __restrict__ items,
                                                const int* __restrict__ samples,
                                                const float* __restrict__ bias,
                                                float* __restrict__ out, int S) {
    __shared__ float item_sh[DIM];
    __shared__ float bias_sh[DIM];
    const int b = blockIdx.x;
    const int t = threadIdx.x;

    const int item = __ldg(items + b);
    {
        float bv = __ldg(bias + t);
        bias_sh[t] = bv;
        item_sh[t] = g_nodes[(size_t)item * DIM + t] + bv;
    }
    __syncthreads();

    const int warp = t >> 5;
    const int lane = t & 31;
    const float4 iv = reinterpret_cast<const float4*>(item_sh)[lane];
    const float4 bv = reinterpret_cast<const float4*>(bias_sh)[lane];

    const int* samp = samples + (size_t)b * S;
#pragma unroll 4
    for (int i = 0; i < 16; i++) {
        int s = warp * 16 + i;
        int sidx = __ldg(samp + s);
        const float4 sv = reinterpret_cast<const float4*>(g_nodes)[(size_t)sidx * 32 + lane];
        float p = iv.x * (sv.x + bv.x) + iv.y * (sv.y + bv.y) +
                  iv.z * (sv.z + bv.z) + iv.w * (sv.w + bv.w);
#pragma unroll
        for (int off = 16; off > 0; off >>= 1)
            p += __shfl_xor_sync(0xffffffffu, p, off);
        if (lane == 0) out[(size_t)b * S + s] = p;
    }
}

// ---------------------------------------------------------------------------
// launcher
// ---------------------------------------------------------------------------
extern "C" void kernel_launch(void* const* d_in, const int* in_sizes, int n_in,
                              void* d_out, int out_size) {
    const int*   items   = (const int*)d_in[0];
    const int*   samples = (const int*)d_in[1];
    const int*   edge    = (const int*)d_in[2];
    const float* emb     = (const float*)d_in[3];
    const float* W       = (const float*)d_in[4];
    const float* bias    = (const float*)d_in[5];
    float*       out     = (float*)d_out;

    const int B = in_sizes[0];
    const int S = in_sizes[1] / B;
    const int E = in_sizes[2] / 2;
    const int V = in_sizes[3] / DIM;

    // prep (deg=1 + W transpose/split), degrees
    k_prep<<<(V + 255) / 256, 256>>>(W, V);
    k_deg<<<(E + 255) / 256, 256>>>(edge, E);
    k_dinv<<<(V + 255) / 256, 256>>>(V);

    // tensor-core GEMM + fused self-loop/scaling (2 CTAs/SM)
    cudaFuncSetAttribute(k_gemm, cudaFuncAttributeMaxDynamicSharedMemorySize, GEMM_SMEM);
    k_gemm<<<(V + TILE_M - 1) / TILE_M, 256, GEMM_SMEM>>>(emb, V);

    // edge scatter-add
    k_edge_agg<<<(E + 7) / 8, 256>>>(edge, E);

    // scoring with folded bias
    k_scores<<<B, 128>>>(items, samples, bias, out, S);
}

// round 9
// speedup vs baseline: 1.4232x; 1.1802x over previous
#include <cuda_runtime.h>
#include <cuda_bf16.h>
#include <cstdint>

#define DIM 128
#define TILE_M 64
#define MAXV 100000
#define SH 136            // padded smem row stride in bf16 halves (272B)
#define CAP 128           // in-adjacency bucket capacity per node

// ---------------------------------------------------------------------------
// Device globals (no allocation allowed)
// ---------------------------------------------------------------------------
__device__ float g_h[MAXV * DIM];      // dinv[v] * (emb @ W)[v]
__device__ float g_nodes[MAXV * DIM];  // dinv^2*h (self-loop), then full agg
__device__ int   g_cnt[MAXV];          // in-degree (excl. self-loop)
__device__ float g_dinv[MAXV];
__device__ int   g_adj[(size_t)MAXV * CAP];   // in-adjacency buckets (51MB)
// W transposed + bf16-split: g_w1[n*128+k] = bf16_hi(W[k][n]), g_w2 = residual
__device__ __align__(16) __nv_bfloat16 g_w1[DIM * DIM];
__device__ __align__(16) __nv_bfloat16 g_w2[DIM * DIM];

// ---------------------------------------------------------------------------
// mma.sync bf16 m16n8k16 (row.col, f32 accum) — supported on base sm_100
// ---------------------------------------------------------------------------
#define MMA_BF16(c, a, b0, b1)                                              \
    asm volatile(                                                           \
        "mma.sync.aligned.m16n8k16.row.col.f32.bf16.bf16.f32 "              \
        "{%0,%1,%2,%3}, {%4,%5,%6,%7}, {%8,%9}, {%0,%1,%2,%3};"             \
        : "+f"((c)[0]), "+f"((c)[1]), "+f"((c)[2]), "+f"((c)[3])            \
        : "r"((a)[0]), "r"((a)[1]), "r"((a)[2]), "r"((a)[3]),               \
          "r"(b0), "r"(b1))

__device__ __forceinline__ uint32_t ld32h(const __nv_bfloat16* p, int off_halves) {
    return *reinterpret_cast<const uint32_t*>(p + off_halves);
}
__device__ __forceinline__ uint32_t pack_bf2(__nv_bfloat16 lo, __nv_bfloat16 hi) {
    __nv_bfloat162 v(lo, hi);
    return *reinterpret_cast<uint32_t*>(&v);
}

// ---------------------------------------------------------------------------
// prep: zero in-degree counters + transpose/split W
// ---------------------------------------------------------------------------
__global__ void k_prep(const float* __restrict__ W, int V) {
    int gid = blockIdx.x * blockDim.x + threadIdx.x;
    if (gid < V) g_cnt[gid] = 0;
    if (gid < DIM * DIM) {
        int k = gid >> 7;
        int n = gid & 127;
        float x = W[gid];
        __nv_bfloat16 hi = __float2bfloat16(x);
        __nv_bfloat16 lo = __float2bfloat16(x - __bfloat162float(hi));
        g_w1[n * DIM + k] = hi;
        g_w2[n * DIM + k] = lo;
    }
}

// histogram + bucket scatter in one pass
__global__ void k_fill(const int* __restrict__ edge, int E) {
    int e = blockIdx.x * blockDim.x + threadIdx.x;
    if (e >= E) return;
    int src = __ldg(edge + e);          // edge_index[0]
    int dst = __ldg(edge + E + e);      // edge_index[1]
    int c = atomicAdd(&g_cnt[dst], 1);
    if (c < CAP) g_adj[(size_t)dst * CAP + c] = src;
}

__global__ void k_dinv(int V) {
    int v = blockIdx.x * blockDim.x + threadIdx.x;
    if (v < V) g_dinv[v] = rsqrtf(1.0f + (float)g_cnt[v]);  // +1 self-loop
}

// ---------------------------------------------------------------------------
// Tensor-core GEMM (mma.sync bf16, 3-pass split: x1w1 + x1w2 + x2w1).
// CTA: 256 thr = 8 warps; tile 64 rows x 128 cols; 2 CTAs/SM.
// ---------------------------------------------------------------------------
#define X1_OFF 0
#define X2_OFF (TILE_M * SH * 2)
#define W1_OFF (2 * TILE_M * SH * 2)
#define W2_OFF (W1_OFF + DIM * SH * 2)
#define DINV_OFF (W2_OFF + DIM * SH * 2)
#define GEMM_SMEM (DINV_OFF + 256)
#define STAGE_STRIDE 132

__global__ void __launch_bounds__(256, 2) k_gemm(const float* __restrict__ X, int V) {
    extern __shared__ __align__(16) unsigned char smem[];
    __nv_bfloat16* x1 = reinterpret_cast<__nv_bfloat16*>(smem + X1_OFF);
    __nv_bfloat16* x2 = reinterpret_cast<__nv_bfloat16*>(smem + X2_OFF);
    __nv_bfloat16* w1 = reinterpret_cast<__nv_bfloat16*>(smem + W1_OFF);
    __nv_bfloat16* w2 = reinterpret_cast<__nv_bfloat16*>(smem + W2_OFF);
    float* dinv_sh = reinterpret_cast<float*>(smem + DINV_OFF);

    const int tid = threadIdx.x;
    const int wid = tid >> 5;
    const int lane = tid & 31;
    const int row0 = blockIdx.x * TILE_M;

    if (tid < TILE_M) {
        int r = row0 + tid;
        dinv_sh[tid] = (r < V) ? g_dinv[r] : 0.0f;
    }

    // Copy W tiles into padded smem
    {
        const uint4* s1 = reinterpret_cast<const uint4*>(g_w1);
        const uint4* s2 = reinterpret_cast<const uint4*>(g_w2);
#pragma unroll
        for (int i = 0; i < 8; i++) {
            int idx = tid + i * 256;
            int r = idx >> 4;
            int c = idx & 15;
            reinterpret_cast<uint4*>(w1 + r * SH)[c] = s1[idx];
            reinterpret_cast<uint4*>(w2 + r * SH)[c] = s2[idx];
        }
    }
    // Load + split X: 64 rows x 32 float4 = 2048; 8 per thread
    {
        const float4* X4 = reinterpret_cast<const float4*>(X);
#pragma unroll
        for (int i = 0; i < 8; i++) {
            int idx = tid + i * 256;
            int r = idx >> 5;
            int c4 = idx & 31;
            float4 v = make_float4(0.f, 0.f, 0.f, 0.f);
            if (row0 + r < V) v = X4[(size_t)(row0 + r) * 32 + c4];
            __nv_bfloat16 h0 = __float2bfloat16(v.x);
            __nv_bfloat16 h1 = __float2bfloat16(v.y);
            __nv_bfloat16 h2 = __float2bfloat16(v.z);
            __nv_bfloat16 h3 = __float2bfloat16(v.w);
            __nv_bfloat16 l0 = __float2bfloat16(v.x - __bfloat162float(h0));
            __nv_bfloat16 l1 = __float2bfloat16(v.y - __bfloat162float(h1));
            __nv_bfloat16 l2 = __float2bfloat16(v.z - __bfloat162float(h2));
            __nv_bfloat16 l3 = __float2bfloat16(v.w - __bfloat162float(h3));
            uint2 hp = make_uint2(pack_bf2(h0, h1), pack_bf2(h2, h3));
            uint2 lp = make_uint2(pack_bf2(l0, l1), pack_bf2(l2, l3));
            *reinterpret_cast<uint2*>(x1 + r * SH + c4 * 4) = hp;
            *reinterpret_cast<uint2*>(x2 + r * SH + c4 * 4) = lp;
        }
    }
    __syncthreads();

    const int wr = (wid & 1) * 32;
    const int wc = (wid >> 1) * 32;
    const int g = lane >> 2;
    const int tg = lane & 3;

    float acc[2][4][4];
#pragma unroll
    for (int mt = 0; mt < 2; mt++)
#pragma unroll
        for (int nt = 0; nt < 4; nt++)
#pragma unroll
            for (int j = 0; j < 4; j++) acc[mt][nt][j] = 0.0f;

#pragma unroll
    for (int kb = 0; kb < DIM; kb += 16) {
        uint32_t ah[2][4], al[2][4];
#pragma unroll
        for (int mt = 0; mt < 2; mt++) {
            int rb = wr + mt * 16;
            int o0 = (rb + g) * SH + kb + 2 * tg;
            int o1 = (rb + g + 8) * SH + kb + 2 * tg;
            ah[mt][0] = ld32h(x1, o0);
            ah[mt][1] = ld32h(x1, o1);
            ah[mt][2] = ld32h(x1, o0 + 8);
            ah[mt][3] = ld32h(x1, o1 + 8);
            al[mt][0] = ld32h(x2, o0);
            al[mt][1] = ld32h(x2, o1);
            al[mt][2] = ld32h(x2, o0 + 8);
            al[mt][3] = ld32h(x2, o1 + 8);
        }
#pragma unroll
        for (int nt = 0; nt < 4; nt++) {
            int nb = (wc + nt * 8 + g) * SH + kb + 2 * tg;
            uint32_t bh0 = ld32h(w1, nb);
            uint32_t bh1 = ld32h(w1, nb + 8);
            uint32_t bl0 = ld32h(w2, nb);
            uint32_t bl1 = ld32h(w2, nb + 8);
#pragma unroll
            for (int mt = 0; mt < 2; mt++) {
                MMA_BF16(acc[mt][nt], ah[mt], bh0, bh1);
                MMA_BF16(acc[mt][nt], ah[mt], bl0, bl1);
                MMA_BF16(acc[mt][nt], al[mt], bh0, bh1);
            }
        }
    }
    __syncthreads();   // x1/x2 become the epilogue stage

    {
        float* stage = reinterpret_cast<float*>(smem);
#pragma unroll
        for (int mt = 0; mt < 2; mt++) {
#pragma unroll
            for (int nt = 0; nt < 4; nt++) {
                int rs = wr + mt * 16 + g;
                int cs = wc + nt * 8 + 2 * tg;
                stage[rs * STAGE_STRIDE + cs]           = acc[mt][nt][0];
                stage[rs * STAGE_STRIDE + cs + 1]       = acc[mt][nt][1];
                stage[(rs + 8) * STAGE_STRIDE + cs]     = acc[mt][nt][2];
                stage[(rs + 8) * STAGE_STRIDE + cs + 1] = acc[mt][nt][3];
            }
        }
    }
    __syncthreads();

    {
        const float* stage = reinterpret_cast<const float*>(smem);
#pragma unroll
        for (int i = 0; i < 8; i++) {
            int idx = tid + i * 256;
            int m = idx >> 5;
            int c4 = idx & 31;
            int row = row0 + m;
            if (row < V) {
                const float4 v = *reinterpret_cast<const float4*>(
                    stage + m * STAGE_STRIDE + c4 * 4);
                float s = dinv_sh[m];
                float s2 = s * s;
                size_t off = (size_t)row * 32 + c4;
                reinterpret_cast<float4*>(g_h)[off] =
                    make_float4(v.x * s, v.y * s, v.z * s, v.w * s);
                reinterpret_cast<float4*>(g_nodes)[off] =
                    make_float4(v.x * s2, v.y * s2, v.z * s2, v.w * s2);
            }
        }
    }
}

// ---------------------------------------------------------------------------
// gather aggregation: warp per node v.
// nodes[v] = dinv^2*h[v] (already there) + dinv[v] * sum_{src in adj[v]} g_h[src]
// ---------------------------------------------------------------------------
__global__ void __launch_bounds__(256) k_gather(int V) {
    int v = (blockIdx.x * blockDim.x + threadIdx.x) >> 5;
    int lane = threadIdx.x & 31;
    if (v >= V) return;

    int cnt = g_cnt[v];
    if (cnt > CAP) cnt = CAP;

    float4 s = make_float4(0.f, 0.f, 0.f, 0.f);
    const float4* H = reinterpret_cast<const float4*>(g_h);
    const int* adj = g_adj + (size_t)v * CAP;

    for (int base = 0; base < cnt; base += 32) {
        int n = cnt - base;
        if (n > 32) n = 32;
        int src = (lane < n) ? __ldg(adj + base + lane) : 0;
        for (int i = 0; i < n; i++) {
            int sj = __shfl_sync(0xffffffffu, src, i);
            float4 hv = H[(size_t)sj * 32 + lane];
            s.x += hv.x; s.y += hv.y; s.z += hv.z; s.w += hv.w;
        }
    }

    float dv = __ldg(g_dinv + v);
    float4* N = reinterpret_cast<float4*>(g_nodes) + (size_t)v * 32 + lane;
    float4 acc = *N;
    acc.x = fmaf(dv, s.x, acc.x);
    acc.y = fmaf(dv, s.y, acc.y);
    acc.z = fmaf(dv, s.z, acc.z);
    acc.w = fmaf(dv, s.w, acc.w);
    *N = acc;
}

// ---------------------------------------------------------------------------
// scoring: block = one item; 4 warps x 16 samples; bias folded in.
// ---------------------------------------------------------------------------
__global__ void __launch_bounds__(128) k_scores(const int* __restrict__ items,
                                                const int* __restrict__ samples,
                                                const float* __restrict__ bias,
                                                float* __restrict__ out, int S) {
    __shared__ float item_sh[DIM];
    __shared__ float bias_sh[DIM];
    const int b = blockIdx.x;
    const int t = threadIdx.x;

    const int item = __ldg(items + b);
    {
        float bv = __ldg(bias + t);
        bias_sh[t] = bv;
        item_sh[t] = g_nodes[(size_t)item * DIM + t] + bv;
    }
    __syncthreads();

    const int warp = t >> 5;
    const int lane = t & 31;
    const float4 iv = reinterpret_cast<const float4*>(item_sh)[lane];
    const float4 bv = reinterpret_cast<const float4*>(bias_sh)[lane];

    const int* samp = samples + (size_t)b * S;
#pragma unroll 4
    for (int i = 0; i < 16; i++) {
        int s = warp * 16 + i;
        int sidx = __ldg(samp + s);
        const float4 sv = reinterpret_cast<const float4*>(g_nodes)[(size_t)sidx * 32 + lane];
        float p = iv.x * (sv.x + bv.x) + iv.y * (sv.y + bv.y) +
                  iv.z * (sv.z + bv.z) + iv.w * (sv.w + bv.w);
#pragma unroll
        for (int off = 16; off > 0; off >>= 1)
            p += __shfl_xor_sync(0xffffffffu, p, off);
        if (lane == 0) out[(size_t)b * S + s] = p;
    }
}

// ---------------------------------------------------------------------------
// launcher
// ---------------------------------------------------------------------------
extern "C" void kernel_launch(void* const* d_in, const int* in_sizes, int n_in,
                              void* d_out, int out_size) {
    const int*   items   = (const int*)d_in[0];
    const int*   samples = (const int*)d_in[1];
    const int*   edge    = (const int*)d_in[2];
    const float* emb     = (const float*)d_in[3];
    const float* W       = (const float*)d_in[4];
    const float* bias    = (const float*)d_in[5];
    float*       out     = (float*)d_out;

    const int B = in_sizes[0];
    const int S = in_sizes[1] / B;
    const int E = in_sizes[2] / 2;
    const int V = in_sizes[3] / DIM;

    // prep (zero counts + W split), adjacency build, dinv
    k_prep<<<(V + 255) / 256, 256>>>(W, V);
    k_fill<<<(E + 255) / 256, 256>>>(edge, E);
    k_dinv<<<(V + 255) / 256, 256>>>(V);

    // tensor-core GEMM + fused self-loop/scaling (2 CTAs/SM)
    cudaFuncSetAttribute(k_gemm, cudaFuncAttributeMaxDynamicSharedMemorySize, GEMM_SMEM);
    k_gemm<<<(V + TILE_M - 1) / TILE_M, 256, GEMM_SMEM>>>(emb, V);

    // gather aggregation (warp per node)
    k_gather<<<(V + 7) / 8, 256>>>(V);

    // scoring with folded bias
    k_scores<<<B, 128>>>(items, samples, bias, out, S);
}

// round 10
// speedup vs baseline: 1.5301x; 1.0751x over previous
#include <cuda_runtime.h>
#include <cuda_bf16.h>
#include <cstdint>

#define DIM 128
#define TILE_M 64
#define MAXV 100000
#define SH 136            // padded smem row stride in bf16 halves (272B)
#define CAP 128           // in-adjacency bucket capacity per node

// ---------------------------------------------------------------------------
// Device globals (no allocation allowed)
// ---------------------------------------------------------------------------
__device__ float g_h[MAXV * DIM];      // dinv[v] * (emb @ W)[v]
__device__ float g_nodes[MAXV * DIM];  // final aggregated features
__device__ int   g_cnt[MAXV];          // in-degree (excl. self-loop)
__device__ float g_dinv[MAXV];
__device__ int   g_adj[(size_t)MAXV * CAP];   // in-adjacency buckets (51MB)
// W transposed + bf16-split: g_w1[n*128+k] = bf16_hi(W[k][n]), g_w2 = residual
__device__ __align__(16) __nv_bfloat16 g_w1[DIM * DIM];
__device__ __align__(16) __nv_bfloat16 g_w2[DIM * DIM];

// ---------------------------------------------------------------------------
// mma.sync bf16 m16n8k16 (row.col, f32 accum) + ldmatrix — base sm_100 OK
// ---------------------------------------------------------------------------
#define MMA_BF16(c, a, b0, b1)                                              \
    asm volatile(                                                           \
        "mma.sync.aligned.m16n8k16.row.col.f32.bf16.bf16.f32 "              \
        "{%0,%1,%2,%3}, {%4,%5,%6,%7}, {%8,%9}, {%0,%1,%2,%3};"             \
        : "+f"((c)[0]), "+f"((c)[1]), "+f"((c)[2]), "+f"((c)[3])            \
        : "r"((a)[0]), "r"((a)[1]), "r"((a)[2]), "r"((a)[3]),               \
          "r"(b0), "r"(b1))

#define LDSM_X4(r0, r1, r2, r3, addr)                                       \
    asm volatile(                                                           \
        "ldmatrix.sync.aligned.m8n8.x4.shared.b16 {%0,%1,%2,%3}, [%4];"     \
        : "=r"(r0), "=r"(r1), "=r"(r2), "=r"(r3) : "r"(addr))

__device__ __forceinline__ uint32_t smem_u32(const void* p) {
    uint32_t a;
    asm("{ .reg .u64 t; cvta.to.shared.u64 t, %1; cvt.u32.u64 %0, t; }"
        : "=r"(a) : "l"(p));
    return a;
}
__device__ __forceinline__ uint32_t pack_bf2(__nv_bfloat16 lo, __nv_bfloat16 hi) {
    __nv_bfloat162 v(lo, hi);
    return *reinterpret_cast<uint32_t*>(&v);
}

// ---------------------------------------------------------------------------
// prep: zero in-degree counters + transpose/split W
// ---------------------------------------------------------------------------
__global__ void k_prep(const float* __restrict__ W, int V) {
    int gid = blockIdx.x * blockDim.x + threadIdx.x;
    if (gid < V) g_cnt[gid] = 0;
    if (gid < DIM * DIM) {
        int k = gid >> 7;
        int n = gid & 127;
        float x = W[gid];
        __nv_bfloat16 hi = __float2bfloat16(x);
        __nv_bfloat16 lo = __float2bfloat16(x - __bfloat162float(hi));
        g_w1[n * DIM + k] = hi;
        g_w2[n * DIM + k] = lo;
    }
}

// histogram + bucket scatter in one pass
__global__ void k_fill(const int* __restrict__ edge, int E) {
    int e = blockIdx.x * blockDim.x + threadIdx.x;
    if (e >= E) return;
    int src = __ldg(edge + e);          // edge_index[0]
    int dst = __ldg(edge + E + e);      // edge_index[1]
    int c = atomicAdd(&g_cnt[dst], 1);
    if (c < CAP) g_adj[(size_t)dst * CAP + c] = src;
}

__global__ void k_dinv(int V) {
    int v = blockIdx.x * blockDim.x + threadIdx.x;
    if (v < V) g_dinv[v] = rsqrtf(1.0f + (float)g_cnt[v]);  // +1 self-loop
}

// ---------------------------------------------------------------------------
// Tensor-core GEMM (mma.sync bf16, 3-pass split: x1w1 + x1w2 + x2w1).
// Fragment loads via ldmatrix.x4 (8 LDSM vs 48 LDS.32 per warp per k-step).
// CTA: 256 thr = 8 warps; tile 64 rows x 128 cols; 2 CTAs/SM.
// Writes only g_h = dinv * (X@W); g_nodes produced entirely by k_gather.
// ---------------------------------------------------------------------------
#define X1_OFF 0
#define X2_OFF (TILE_M * SH * 2)
#define W1_OFF (2 * TILE_M * SH * 2)
#define W2_OFF (W1_OFF + DIM * SH * 2)
#define DINV_OFF (W2_OFF + DIM * SH * 2)
#define GEMM_SMEM (DINV_OFF + 256)
#define STAGE_STRIDE 132

__global__ void __launch_bounds__(256, 2) k_gemm(const float* __restrict__ X, int V) {
    extern __shared__ __align__(16) unsigned char smem[];
    __nv_bfloat16* x1 = reinterpret_cast<__nv_bfloat16*>(smem + X1_OFF);
    __nv_bfloat16* x2 = reinterpret_cast<__nv_bfloat16*>(smem + X2_OFF);
    __nv_bfloat16* w1 = reinterpret_cast<__nv_bfloat16*>(smem + W1_OFF);
    __nv_bfloat16* w2 = reinterpret_cast<__nv_bfloat16*>(smem + W2_OFF);
    float* dinv_sh = reinterpret_cast<float*>(smem + DINV_OFF);

    const int tid = threadIdx.x;
    const int wid = tid >> 5;
    const int lane = tid & 31;
    const int row0 = blockIdx.x * TILE_M;
    const uint32_t sbase = smem_u32(smem);

    if (tid < TILE_M) {
        int r = row0 + tid;
        dinv_sh[tid] = (r < V) ? g_dinv[r] : 0.0f;
    }

    // Copy W tiles into padded smem
    {
        const uint4* s1 = reinterpret_cast<const uint4*>(g_w1);
        const uint4* s2 = reinterpret_cast<const uint4*>(g_w2);
#pragma unroll
        for (int i = 0; i < 8; i++) {
            int idx = tid + i * 256;
            int r = idx >> 4;
            int c = idx & 15;
            reinterpret_cast<uint4*>(w1 + r * SH)[c] = s1[idx];
            reinterpret_cast<uint4*>(w2 + r * SH)[c] = s2[idx];
        }
    }
    // Load + split X: 64 rows x 32 float4 = 2048; 8 per thread
    {
        const float4* X4 = reinterpret_cast<const float4*>(X);
#pragma unroll
        for (int i = 0; i < 8; i++) {
            int idx = tid + i * 256;
            int r = idx >> 5;
            int c4 = idx & 31;
            float4 v = make_float4(0.f, 0.f, 0.f, 0.f);
            if (row0 + r < V) v = X4[(size_t)(row0 + r) * 32 + c4];
            __nv_bfloat16 h0 = __float2bfloat16(v.x);
            __nv_bfloat16 h1 = __float2bfloat16(v.y);
            __nv_bfloat16 h2 = __float2bfloat16(v.z);
            __nv_bfloat16 h3 = __float2bfloat16(v.w);
            __nv_bfloat16 l0 = __float2bfloat16(v.x - __bfloat162float(h0));
            __nv_bfloat16 l1 = __float2bfloat16(v.y - __bfloat162float(h1));
            __nv_bfloat16 l2 = __float2bfloat16(v.z - __bfloat162float(h2));
            __nv_bfloat16 l3 = __float2bfloat16(v.w - __bfloat162float(h3));
            uint2 hp = make_uint2(pack_bf2(h0, h1), pack_bf2(h2, h3));
            uint2 lp = make_uint2(pack_bf2(l0, l1), pack_bf2(l2, l3));
            *reinterpret_cast<uint2*>(x1 + r * SH + c4 * 4) = hp;
            *reinterpret_cast<uint2*>(x2 + r * SH + c4 * 4) = lp;
        }
    }
    __syncthreads();

    const int wr = (wid & 1) * 32;       // warp rows
    const int wc = (wid >> 1) * 32;      // warp cols
    const int g = lane >> 2;
    const int tg = lane & 3;

    // ldmatrix per-thread base addresses (bytes, shared space)
    // A (m16k16 x4): rows rb+(lane&15), k-col (lane>>4)*8
    const uint32_t a_row = (uint32_t)((wr + (lane & 15)) * SH + (lane >> 4) * 8) * 2;
    const uint32_t aoff_mt = 16 * SH * 2;  // +16 rows
    // B (two n-tiles per x4): n = wc + (2p + (lane>>4))*8 + (lane&7),
    //                         k-col ((lane>>3)&1)*8
    uint32_t b_row[2];
#pragma unroll
    for (int p = 0; p < 2; p++)
        b_row[p] = (uint32_t)((wc + (2 * p + (lane >> 4)) * 8 + (lane & 7)) * SH +
                              ((lane >> 3) & 1) * 8) * 2;

    float acc[2][4][4];
#pragma unroll
    for (int mt = 0; mt < 2; mt++)
#pragma unroll
        for (int nt = 0; nt < 4; nt++)
#pragma unroll
            for (int j = 0; j < 4; j++) acc[mt][nt][j] = 0.0f;

#pragma unroll
    for (int kb = 0; kb < DIM; kb += 16) {
        const uint32_t koff = (uint32_t)kb * 2;
        uint32_t ah[2][4], al[2][4];
#pragma unroll
        for (int mt = 0; mt < 2; mt++) {
            LDSM_X4(ah[mt][0], ah[mt][1], ah[mt][2], ah[mt][3],
                    sbase + X1_OFF + a_row + mt * aoff_mt + koff);
            LDSM_X4(al[mt][0], al[mt][1], al[mt][2], al[mt][3],
                    sbase + X2_OFF + a_row + mt * aoff_mt + koff);
        }
        uint32_t bh0[4], bh1[4], bl0[4], bl1[4];
#pragma unroll
        for (int p = 0; p < 2; p++) {
            LDSM_X4(bh0[2 * p], bh1[2 * p], bh0[2 * p + 1], bh1[2 * p + 1],
                    sbase + W1_OFF + b_row[p] + koff);
            LDSM_X4(bl0[2 * p], bl1[2 * p], bl0[2 * p + 1], bl1[2 * p + 1],
                    sbase + W2_OFF + b_row[p] + koff);
        }
#pragma unroll
        for (int nt = 0; nt < 4; nt++)
#pragma unroll
            for (int mt = 0; mt < 2; mt++) {
                MMA_BF16(acc[mt][nt], ah[mt], bh0[nt], bh1[nt]);
                MMA_BF16(acc[mt][nt], ah[mt], bl0[nt], bl1[nt]);
                MMA_BF16(acc[mt][nt], al[mt], bh0[nt], bh1[nt]);
            }
    }
    __syncthreads();   // x1/x2 become the epilogue stage

    // Stage accumulators
    {
        float* stage = reinterpret_cast<float*>(smem);
#pragma unroll
        for (int mt = 0; mt < 2; mt++) {
#pragma unroll
            for (int nt = 0; nt < 4; nt++) {
                int rs = wr + mt * 16 + g;
                int cs = wc + nt * 8 + 2 * tg;
                stage[rs * STAGE_STRIDE + cs]           = acc[mt][nt][0];
                stage[rs * STAGE_STRIDE + cs + 1]       = acc[mt][nt][1];
                stage[(rs + 8) * STAGE_STRIDE + cs]     = acc[mt][nt][2];
                stage[(rs + 8) * STAGE_STRIDE + cs + 1] = acc[mt][nt][3];
            }
        }
    }
    __syncthreads();

    // Coalesced store: g_h = dinv * D only
    {
        const float* stage = reinterpret_cast<const float*>(smem);
#pragma unroll
        for (int i = 0; i < 8; i++) {
            int idx = tid + i * 256;
            int m = idx >> 5;
            int c4 = idx & 31;
            int row = row0 + m;
            if (row < V) {
                const float4 v = *reinterpret_cast<const float4*>(
                    stage + m * STAGE_STRIDE + c4 * 4);
                float s = dinv_sh[m];
                reinterpret_cast<float4*>(g_h)[(size_t)row * 32 + c4] =
                    make_float4(v.x * s, v.y * s, v.z * s, v.w * s);
            }
        }
    }
}

// ---------------------------------------------------------------------------
// gather aggregation: warp per node v.
// nodes[v] = dinv[v] * ( g_h[v]  +  sum_{src in adj[v]} g_h[src] )
// ---------------------------------------------------------------------------
__global__ void __launch_bounds__(256) k_gather(int V) {
    int v = (blockIdx.x * blockDim.x + threadIdx.x) >> 5;
    int lane = threadIdx.x & 31;
    if (v >= V) return;

    int cnt = g_cnt[v];
    if (cnt > CAP) cnt = CAP;

    const float4* H = reinterpret_cast<const float4*>(g_h);
    float4 s = H[(size_t)v * 32 + lane];     // self-loop term (g_h[v])
    const int* adj = g_adj + (size_t)v * CAP;

    for (int base = 0; base < cnt; base += 32) {
        int n = cnt - base;
        if (n > 32) n = 32;
        int src = (lane < n) ? __ldg(adj + base + lane) : 0;
        for (int i = 0; i < n; i++) {
            int sj = __shfl_sync(0xffffffffu, src, i);
            float4 hv = H[(size_t)sj * 32 + lane];
            s.x += hv.x; s.y += hv.y; s.z += hv.z; s.w += hv.w;
        }
    }

    float dv = __ldg(g_dinv + v);
    reinterpret_cast<float4*>(g_nodes)[(size_t)v * 32 + lane] =
        make_float4(dv * s.x, dv * s.y, dv * s.z, dv * s.w);
}

// ---------------------------------------------------------------------------
// scoring: block = one item; 4 warps x 16 samples; bias folded in.
// ---------------------------------------------------------------------------
__global__ void __launch_bounds__(128) k_scores(const int* __restrict__ items,
                                                const int* __restrict__ samples,
                                                const float* __restrict__ bias,
                                                float* __restrict__ out, int S) {
    __shared__ float item_sh[DIM];
    __shared__ float bias_sh[DIM];
    const int b = blockIdx.x;
    const int t = threadIdx.x;

    const int item = __ldg(items + b);
    {
        float bv = __ldg(bias + t);
        bias_sh[t] = bv;
        item_sh[t] = g_nodes[(size_t)item * DIM + t] + bv;
    }
    __syncthreads();

    const int warp = t >> 5;
    const int lane = t & 31;
    const float4 iv = reinterpret_cast<const float4*>(item_sh)[lane];
    const float4 bv = reinterpret_cast<const float4*>(bias_sh)[lane];

    const int* samp = samples + (size_t)b * S;
#pragma unroll 4
    for (int i = 0; i < 16; i++) {
        int s = warp * 16 + i;
        int sidx = __ldg(samp + s);
        const float4 sv = reinterpret_cast<const float4*>(g_nodes)[(size_t)sidx * 32 + lane];
        float p = iv.x * (sv.x + bv.x) + iv.y * (sv.y + bv.y) +
                  iv.z * (sv.z + bv.z) + iv.w * (sv.w + bv.w);
#pragma unroll
        for (int off = 16; off > 0; off >>= 1)
            p += __shfl_xor_sync(0xffffffffu, p, off);
        if (lane == 0) out[(size_t)b * S + s] = p;
    }
}

// ---------------------------------------------------------------------------
// launcher
// ---------------------------------------------------------------------------
extern "C" void kernel_launch(void* const* d_in, const int* in_sizes, int n_in,
                              void* d_out, int out_size) {
    const int*   items   = (const int*)d_in[0];
    const int*   samples = (const int*)d_in[1];
    const int*   edge    = (const int*)d_in[2];
    const float* emb     = (const float*)d_in[3];
    const float* W       = (const float*)d_in[4];
    const float* bias    = (const float*)d_in[5];
    float*       out     = (float*)d_out;

    const int B = in_sizes[0];
    const int S = in_sizes[1] / B;
    const int E = in_sizes[2] / 2;
    const int V = in_sizes[3] / DIM;

    // prep (zero counts + W split), adjacency build, dinv
    k_prep<<<(V + 255) / 256, 256>>>(W, V);
    k_fill<<<(E + 255) / 256, 256>>>(edge, E);
    k_dinv<<<(V + 255) / 256, 256>>>(V);

    // tensor-core GEMM (ldmatrix + mma.sync), writes g_h only
    cudaFuncSetAttribute(k_gemm, cudaFuncAttributeMaxDynamicSharedMemorySize, GEMM_SMEM);
    k_gemm<<<(V + TILE_M - 1) / TILE_M, 256, GEMM_SMEM>>>(emb, V);

    // gather aggregation (warp per node) -> g_nodes
    k_gather<<<(V + 7) / 8, 256>>>(V);

    // scoring with folded bias
    k_scores<<<B, 128>>>(items, samples, bias, out, S);
}

// round 11
// speedup vs baseline: 1.5875x; 1.0375x over previous
#include <cuda_runtime.h>
#include <cuda_bf16.h>
#include <cuda_fp16.h>
#include <cstdint>

#define DIM 128
#define TILE_M 64
#define MAXV 100000
#define SH 136            // padded smem row stride in bf16 halves (272B)
#define CAP 128           // in-adjacency bucket capacity per node

// ---------------------------------------------------------------------------
// Device globals (no allocation allowed)
// ---------------------------------------------------------------------------
__device__ float g_h[MAXV * DIM];        // dinv[v] * (emb @ W)[v]
__device__ float g_nodes[MAXV * DIM];    // final aggregated features + bias
__device__ __align__(16) __half g_nodes_h[MAXV * DIM];  // fp16 copy for scoring
__device__ int   g_cnt[MAXV];            // in-degree (excl. self-loop)
__device__ float g_dinv[MAXV];
__device__ int   g_adj[(size_t)MAXV * CAP];   // in-adjacency buckets (51MB)
// W transposed + bf16-split: g_w1[n*128+k] = bf16_hi(W[k][n]), g_w2 = residual
__device__ __align__(16) __nv_bfloat16 g_w1[DIM * DIM];
__device__ __align__(16) __nv_bfloat16 g_w2[DIM * DIM];

// ---------------------------------------------------------------------------
// mma.sync bf16 m16n8k16 (row.col, f32 accum) + ldmatrix — base sm_100 OK
// ---------------------------------------------------------------------------
#define MMA_BF16(c, a, b0, b1)                                              \
    asm volatile(                                                           \
        "mma.sync.aligned.m16n8k16.row.col.f32.bf16.bf16.f32 "              \
        "{%0,%1,%2,%3}, {%4,%5,%6,%7}, {%8,%9}, {%0,%1,%2,%3};"             \
        : "+f"((c)[0]), "+f"((c)[1]), "+f"((c)[2]), "+f"((c)[3])            \
        : "r"((a)[0]), "r"((a)[1]), "r"((a)[2]), "r"((a)[3]),               \
          "r"(b0), "r"(b1))

#define LDSM_X4(r0, r1, r2, r3, addr)                                       \
    asm volatile(                                                           \
        "ldmatrix.sync.aligned.m8n8.x4.shared.b16 {%0,%1,%2,%3}, [%4];"     \
        : "=r"(r0), "=r"(r1), "=r"(r2), "=r"(r3) : "r"(addr))

__device__ __forceinline__ uint32_t smem_u32(const void* p) {
    uint32_t a;
    asm("{ .reg .u64 t; cvta.to.shared.u64 t, %1; cvt.u32.u64 %0, t; }"
        : "=r"(a) : "l"(p));
    return a;
}
__device__ __forceinline__ uint32_t pack_bf2(__nv_bfloat16 lo, __nv_bfloat16 hi) {
    __nv_bfloat162 v(lo, hi);
    return *reinterpret_cast<uint32_t*>(&v);
}

// ---------------------------------------------------------------------------
// prep: zero in-degree counters + transpose/split W
// ---------------------------------------------------------------------------
__global__ void k_prep(const float* __restrict__ W, int V) {
    int gid = blockIdx.x * blockDim.x + threadIdx.x;
    if (gid < V) g_cnt[gid] = 0;
    if (gid < DIM * DIM) {
        int k = gid >> 7;
        int n = gid & 127;
        float x = W[gid];
        __nv_bfloat16 hi = __float2bfloat16(x);
        __nv_bfloat16 lo = __float2bfloat16(x - __bfloat162float(hi));
        g_w1[n * DIM + k] = hi;
        g_w2[n * DIM + k] = lo;
    }
}

// histogram + bucket scatter in one pass
__global__ void k_fill(const int* __restrict__ edge, int E) {
    int e = blockIdx.x * blockDim.x + threadIdx.x;
    if (e >= E) return;
    int src = __ldg(edge + e);          // edge_index[0]
    int dst = __ldg(edge + E + e);      // edge_index[1]
    int c = atomicAdd(&g_cnt[dst], 1);
    if (c < CAP) g_adj[(size_t)dst * CAP + c] = src;
}

__global__ void k_dinv(int V) {
    int v = blockIdx.x * blockDim.x + threadIdx.x;
    if (v < V) g_dinv[v] = rsqrtf(1.0f + (float)g_cnt[v]);  // +1 self-loop
}

// ---------------------------------------------------------------------------
// Tensor-core GEMM (mma.sync bf16, 3-pass split: x1w1 + x1w2 + x2w1).
// Fragment loads via ldmatrix.x4. CTA: 256 thr; tile 64x128; 2 CTAs/SM.
// Writes only g_h = dinv * (X@W).
// ---------------------------------------------------------------------------
#define X1_OFF 0
#define X2_OFF (TILE_M * SH * 2)
#define W1_OFF (2 * TILE_M * SH * 2)
#define W2_OFF (W1_OFF + DIM * SH * 2)
#define DINV_OFF (W2_OFF + DIM * SH * 2)
#define GEMM_SMEM (DINV_OFF + 256)
#define STAGE_STRIDE 132

__global__ void __launch_bounds__(256, 2) k_gemm(const float* __restrict__ X, int V) {
    extern __shared__ __align__(16) unsigned char smem[];
    __nv_bfloat16* x1 = reinterpret_cast<__nv_bfloat16*>(smem + X1_OFF);
    __nv_bfloat16* x2 = reinterpret_cast<__nv_bfloat16*>(smem + X2_OFF);
    __nv_bfloat16* w1 = reinterpret_cast<__nv_bfloat16*>(smem + W1_OFF);
    __nv_bfloat16* w2 = reinterpret_cast<__nv_bfloat16*>(smem + W2_OFF);
    float* dinv_sh = reinterpret_cast<float*>(smem + DINV_OFF);

    const int tid = threadIdx.x;
    const int wid = tid >> 5;
    const int lane = tid & 31;
    const int row0 = blockIdx.x * TILE_M;
    const uint32_t sbase = smem_u32(smem);

    if (tid < TILE_M) {
        int r = row0 + tid;
        dinv_sh[tid] = (r < V) ? g_dinv[r] : 0.0f;
    }

    {
        const uint4* s1 = reinterpret_cast<const uint4*>(g_w1);
        const uint4* s2 = reinterpret_cast<const uint4*>(g_w2);
#pragma unroll
        for (int i = 0; i < 8; i++) {
            int idx = tid + i * 256;
            int r = idx >> 4;
            int c = idx & 15;
            reinterpret_cast<uint4*>(w1 + r * SH)[c] = s1[idx];
            reinterpret_cast<uint4*>(w2 + r * SH)[c] = s2[idx];
        }
    }
    {
        const float4* X4 = reinterpret_cast<const float4*>(X);
#pragma unroll
        for (int i = 0; i < 8; i++) {
            int idx = tid + i * 256;
            int r = idx >> 5;
            int c4 = idx & 31;
            float4 v = make_float4(0.f, 0.f, 0.f, 0.f);
            if (row0 + r < V) v = X4[(size_t)(row0 + r) * 32 + c4];
            __nv_bfloat16 h0 = __float2bfloat16(v.x);
            __nv_bfloat16 h1 = __float2bfloat16(v.y);
            __nv_bfloat16 h2 = __float2bfloat16(v.z);
            __nv_bfloat16 h3 = __float2bfloat16(v.w);
            __nv_bfloat16 l0 = __float2bfloat16(v.x - __bfloat162float(h0));
            __nv_bfloat16 l1 = __float2bfloat16(v.y - __bfloat162float(h1));
            __nv_bfloat16 l2 = __float2bfloat16(v.z - __bfloat162float(h2));
            __nv_bfloat16 l3 = __float2bfloat16(v.w - __bfloat162float(h3));
            uint2 hp = make_uint2(pack_bf2(h0, h1), pack_bf2(h2, h3));
            uint2 lp = make_uint2(pack_bf2(l0, l1), pack_bf2(l2, l3));
            *reinterpret_cast<uint2*>(x1 + r * SH + c4 * 4) = hp;
            *reinterpret_cast<uint2*>(x2 + r * SH + c4 * 4) = lp;
        }
    }
    __syncthreads();

    const int wr = (wid & 1) * 32;
    const int wc = (wid >> 1) * 32;
    const int g = lane >> 2;
    const int tg = lane & 3;

    const uint32_t a_row = (uint32_t)((wr + (lane & 15)) * SH + (lane >> 4) * 8) * 2;
    const uint32_t aoff_mt = 16 * SH * 2;
    uint32_t b_row[2];
#pragma unroll
    for (int p = 0; p < 2; p++)
        b_row[p] = (uint32_t)((wc + (2 * p + (lane >> 4)) * 8 + (lane & 7)) * SH +
                              ((lane >> 3) & 1) * 8) * 2;

    float acc[2][4][4];
#pragma unroll
    for (int mt = 0; mt < 2; mt++)
#pragma unroll
        for (int nt = 0; nt < 4; nt++)
#pragma unroll
            for (int j = 0; j < 4; j++) acc[mt][nt][j] = 0.0f;

#pragma unroll
    for (int kb = 0; kb < DIM; kb += 16) {
        const uint32_t koff = (uint32_t)kb * 2;
        uint32_t ah[2][4], al[2][4];
#pragma unroll
        for (int mt = 0; mt < 2; mt++) {
            LDSM_X4(ah[mt][0], ah[mt][1], ah[mt][2], ah[mt][3],
                    sbase + X1_OFF + a_row + mt * aoff_mt + koff);
            LDSM_X4(al[mt][0], al[mt][1], al[mt][2], al[mt][3],
                    sbase + X2_OFF + a_row + mt * aoff_mt + koff);
        }
        uint32_t bh0[4], bh1[4], bl0[4], bl1[4];
#pragma unroll
        for (int p = 0; p < 2; p++) {
            LDSM_X4(bh0[2 * p], bh1[2 * p], bh0[2 * p + 1], bh1[2 * p + 1],
                    sbase + W1_OFF + b_row[p] + koff);
            LDSM_X4(bl0[2 * p], bl1[2 * p], bl0[2 * p + 1], bl1[2 * p + 1],
                    sbase + W2_OFF + b_row[p] + koff);
        }
#pragma unroll
        for (int nt = 0; nt < 4; nt++)
#pragma unroll
            for (int mt = 0; mt < 2; mt++) {
                MMA_BF16(acc[mt][nt], ah[mt], bh0[nt], bh1[nt]);
                MMA_BF16(acc[mt][nt], ah[mt], bl0[nt], bl1[nt]);
                MMA_BF16(acc[mt][nt], al[mt], bh0[nt], bh1[nt]);
            }
    }
    __syncthreads();

    {
        float* stage = reinterpret_cast<float*>(smem);
#pragma unroll
        for (int mt = 0; mt < 2; mt++) {
#pragma unroll
            for (int nt = 0; nt < 4; nt++) {
                int rs = wr + mt * 16 + g;
                int cs = wc + nt * 8 + 2 * tg;
                stage[rs * STAGE_STRIDE + cs]           = acc[mt][nt][0];
                stage[rs * STAGE_STRIDE + cs + 1]       = acc[mt][nt][1];
                stage[(rs + 8) * STAGE_STRIDE + cs]     = acc[mt][nt][2];
                stage[(rs + 8) * STAGE_STRIDE + cs + 1] = acc[mt][nt][3];
            }
        }
    }
    __syncthreads();

    {
        const float* stage = reinterpret_cast<const float*>(smem);
#pragma unroll
        for (int i = 0; i < 8; i++) {
            int idx = tid + i * 256;
            int m = idx >> 5;
            int c4 = idx & 31;
            int row = row0 + m;
            if (row < V) {
                const float4 v = *reinterpret_cast<const float4*>(
                    stage + m * STAGE_STRIDE + c4 * 4);
                float s = dinv_sh[m];
                reinterpret_cast<float4*>(g_h)[(size_t)row * 32 + c4] =
                    make_float4(v.x * s, v.y * s, v.z * s, v.w * s);
            }
        }
    }
}

// ---------------------------------------------------------------------------
// gather aggregation: warp per node v.
// nodes[v] = dinv[v]*( g_h[v] + sum_src g_h[src] ) + bias   (bias folded here)
// Also writes fp16 copy for the scoring gather.
// ---------------------------------------------------------------------------
__global__ void __launch_bounds__(256) k_gather(const float* __restrict__ bias, int V) {
    int v = (blockIdx.x * blockDim.x + threadIdx.x) >> 5;
    int lane = threadIdx.x & 31;
    if (v >= V) return;

    int cnt = g_cnt[v];
    if (cnt > CAP) cnt = CAP;

    const float4* H = reinterpret_cast<const float4*>(g_h);
    float4 s0 = H[(size_t)v * 32 + lane];    // self-loop term (g_h[v])
    float4 s1 = make_float4(0.f, 0.f, 0.f, 0.f);
    const int* adj = g_adj + (size_t)v * CAP;

    for (int base = 0; base < cnt; base += 32) {
        int n = cnt - base;
        if (n > 32) n = 32;
        int src = (lane < n) ? __ldg(adj + base + lane) : 0;
        int i = 0;
        for (; i + 1 < n; i += 2) {
            int sj0 = __shfl_sync(0xffffffffu, src, i);
            int sj1 = __shfl_sync(0xffffffffu, src, i + 1);
            float4 a = H[(size_t)sj0 * 32 + lane];
            float4 b = H[(size_t)sj1 * 32 + lane];
            s0.x += a.x; s0.y += a.y; s0.z += a.z; s0.w += a.w;
            s1.x += b.x; s1.y += b.y; s1.z += b.z; s1.w += b.w;
        }
        if (i < n) {
            int sj = __shfl_sync(0xffffffffu, src, i);
            float4 a = H[(size_t)sj * 32 + lane];
            s0.x += a.x; s0.y += a.y; s0.z += a.z; s0.w += a.w;
        }
    }

    float dv = __ldg(g_dinv + v);
    const float4 bv = reinterpret_cast<const float4*>(bias)[lane];
    float4 r = make_float4(fmaf(dv, s0.x + s1.x, bv.x),
                           fmaf(dv, s0.y + s1.y, bv.y),
                           fmaf(dv, s0.z + s1.z, bv.z),
                           fmaf(dv, s0.w + s1.w, bv.w));
    reinterpret_cast<float4*>(g_nodes)[(size_t)v * 32 + lane] = r;
    __half2 h01 = __floats2half2_rn(r.x, r.y);
    __half2 h23 = __floats2half2_rn(r.z, r.w);
    uint2 hp = make_uint2(*reinterpret_cast<uint32_t*>(&h01),
                          *reinterpret_cast<uint32_t*>(&h23));
    reinterpret_cast<uint2*>(g_nodes_h)[(size_t)v * 32 + lane] = hp;
}

// ---------------------------------------------------------------------------
// scoring: block = one item; 4 warps x 16 samples.
// item row fp32 (bias already folded), sample rows fp16 (half the traffic).
// ---------------------------------------------------------------------------
__global__ void __launch_bounds__(128) k_scores(const int* __restrict__ items,
                                                const int* __restrict__ samples,
                                                float* __restrict__ out, int S) {
    __shared__ float item_sh[DIM];
    const int b = blockIdx.x;
    const int t = threadIdx.x;

    const int item = __ldg(items + b);
    item_sh[t] = g_nodes[(size_t)item * DIM + t];
    __syncthreads();

    const int warp = t >> 5;
    const int lane = t & 31;
    const float4 iv = reinterpret_cast<const float4*>(item_sh)[lane];

    const int* samp = samples + (size_t)b * S;
    const uint2* NH = reinterpret_cast<const uint2*>(g_nodes_h);
#pragma unroll 4
    for (int i = 0; i < 16; i++) {
        int s = warp * 16 + i;
        int sidx = __ldg(samp + s);
        uint2 hv = NH[(size_t)sidx * 32 + lane];
        float2 f0 = __half22float2(*reinterpret_cast<__half2*>(&hv.x));
        float2 f1 = __half22float2(*reinterpret_cast<__half2*>(&hv.y));
        float p = iv.x * f0.x + iv.y * f0.y + iv.z * f1.x + iv.w * f1.y;
#pragma unroll
        for (int off = 16; off > 0; off >>= 1)
            p += __shfl_xor_sync(0xffffffffu, p, off);
        if (lane == 0) out[(size_t)b * S + s] = p;
    }
}

// ---------------------------------------------------------------------------
// launcher
// ---------------------------------------------------------------------------
extern "C" void kernel_launch(void* const* d_in, const int* in_sizes, int n_in,
                              void* d_out, int out_size) {
    const int*   items   = (const int*)d_in[0];
    const int*   samples = (const int*)d_in[1];
    const int*   edge    = (const int*)d_in[2];
    const float* emb     = (const float*)d_in[3];
    const float* W       = (const float*)d_in[4];
    const float* bias    = (const float*)d_in[5];
    float*       out     = (float*)d_out;

    const int B = in_sizes[0];
    const int S = in_sizes[1] / B;
    const int E = in_sizes[2] / 2;
    const int V = in_sizes[3] / DIM;

    // prep (zero counts + W split), adjacency build, dinv
    k_prep<<<(V + 255) / 256, 256>>>(W, V);
    k_fill<<<(E + 255) / 256, 256>>>(edge, E);
    k_dinv<<<(V + 255) / 256, 256>>>(V);

    // tensor-core GEMM (ldmatrix + mma.sync), writes g_h only
    cudaFuncSetAttribute(k_gemm, cudaFuncAttributeMaxDynamicSharedMemorySize, GEMM_SMEM);
    k_gemm<<<(V + TILE_M - 1) / TILE_M, 256, GEMM_SMEM>>>(emb, V);

    // gather aggregation (warp per node) -> g_nodes (+bias) and fp16 copy
    k_gather<<<(V + 7) / 8, 256>>>(bias, V);

    // scoring (fp16 sample rows)
    k_scores<<<B, 128>>>(items, samples, out, S);
}

// round 12
// speedup vs baseline: 1.7148x; 1.0802x over previous
#include <cuda_runtime.h>
#include <cuda_bf16.h>
#include <cuda_fp16.h>
#include <cstdint>

#define DIM 128
#define TILE_M 64
#define MAXV 100000
#define SH 136            // padded smem row stride in bf16 halves (272B)
#define CAP 128           // in-adjacency bucket capacity per node

// ---------------------------------------------------------------------------
// Device globals (no allocation allowed)
// ---------------------------------------------------------------------------
__device__ __align__(16) __half g_h_h[MAXV * DIM];      // fp16 dinv[v]*(emb@W)[v]
__device__ float g_nodes[MAXV * DIM];                   // final features + bias (fp32, items)
__device__ __align__(16) __half g_nodes_h[MAXV * DIM];  // fp16 copy (samples)
__device__ int   g_cnt[MAXV];                           // in-degree (excl. self-loop)
__device__ int   g_adj[(size_t)MAXV * CAP];             // in-adjacency buckets (51MB)
// W transposed + bf16-split: g_w1[n*128+k] = bf16_hi(W[k][n]), g_w2 = residual
__device__ __align__(16) __nv_bfloat16 g_w1[DIM * DIM];
__device__ __align__(16) __nv_bfloat16 g_w2[DIM * DIM];

// ---------------------------------------------------------------------------
// mma.sync bf16 m16n8k16 (row.col, f32 accum) + ldmatrix — base sm_100 OK
// ---------------------------------------------------------------------------
#define MMA_BF16(c, a, b0, b1)                                              \
    asm volatile(                                                           \
        "mma.sync.aligned.m16n8k16.row.col.f32.bf16.bf16.f32 "              \
        "{%0,%1,%2,%3}, {%4,%5,%6,%7}, {%8,%9}, {%0,%1,%2,%3};"             \
        : "+f"((c)[0]), "+f"((c)[1]), "+f"((c)[2]), "+f"((c)[3])            \
        : "r"((a)[0]), "r"((a)[1]), "r"((a)[2]), "r"((a)[3]),               \
          "r"(b0), "r"(b1))

#define LDSM_X4(r0, r1, r2, r3, addr)                                       \
    asm volatile(                                                           \
        "ldmatrix.sync.aligned.m8n8.x4.shared.b16 {%0,%1,%2,%3}, [%4];"     \
        : "=r"(r0), "=r"(r1), "=r"(r2), "=r"(r3) : "r"(addr))

__device__ __forceinline__ uint32_t smem_u32(const void* p) {
    uint32_t a;
    asm("{ .reg .u64 t; cvta.to.shared.u64 t, %1; cvt.u32.u64 %0, t; }"
        : "=r"(a) : "l"(p));
    return a;
}
__device__ __forceinline__ uint32_t pack_bf2(__nv_bfloat16 lo, __nv_bfloat16 hi) {
    __nv_bfloat162 v(lo, hi);
    return *reinterpret_cast<uint32_t*>(&v);
}

// ---------------------------------------------------------------------------
// prep: zero in-degree counters + transpose/split W
// ---------------------------------------------------------------------------
__global__ void k_prep(const float* __restrict__ W, int V) {
    int gid = blockIdx.x * blockDim.x + threadIdx.x;
    if (gid < V) g_cnt[gid] = 0;
    if (gid < DIM * DIM) {
        int k = gid >> 7;
        int n = gid & 127;
        float x = W[gid];
        __nv_bfloat16 hi = __float2bfloat16(x);
        __nv_bfloat16 lo = __float2bfloat16(x - __bfloat162float(hi));
        g_w1[n * DIM + k] = hi;
        g_w2[n * DIM + k] = lo;
    }
}

// histogram + bucket scatter in one pass
__global__ void k_fill(const int* __restrict__ edge, int E) {
    int e = blockIdx.x * blockDim.x + threadIdx.x;
    if (e >= E) return;
    int src = __ldg(edge + e);          // edge_index[0]
    int dst = __ldg(edge + E + e);      // edge_index[1]
    int c = atomicAdd(&g_cnt[dst], 1);
    if (c < CAP) g_adj[(size_t)dst * CAP + c] = src;
}

// ---------------------------------------------------------------------------
// Tensor-core GEMM (mma.sync bf16, 3-pass split: x1w1 + x1w2 + x2w1).
// Fragment loads via ldmatrix.x4. CTA: 256 thr; tile 64x128; 2 CTAs/SM.
// Epilogue: g_h_h = fp16( rsqrt(1+cnt) * (X@W) ).
// ---------------------------------------------------------------------------
#define X1_OFF 0
#define X2_OFF (TILE_M * SH * 2)
#define W1_OFF (2 * TILE_M * SH * 2)
#define W2_OFF (W1_OFF + DIM * SH * 2)
#define DINV_OFF (W2_OFF + DIM * SH * 2)
#define GEMM_SMEM (DINV_OFF + 256)
#define STAGE_STRIDE 132

__global__ void __launch_bounds__(256, 2) k_gemm(const float* __restrict__ X, int V) {
    extern __shared__ __align__(16) unsigned char smem[];
    __nv_bfloat16* x1 = reinterpret_cast<__nv_bfloat16*>(smem + X1_OFF);
    __nv_bfloat16* x2 = reinterpret_cast<__nv_bfloat16*>(smem + X2_OFF);
    __nv_bfloat16* w1 = reinterpret_cast<__nv_bfloat16*>(smem + W1_OFF);
    __nv_bfloat16* w2 = reinterpret_cast<__nv_bfloat16*>(smem + W2_OFF);
    float* dinv_sh = reinterpret_cast<float*>(smem + DINV_OFF);

    const int tid = threadIdx.x;
    const int wid = tid >> 5;
    const int lane = tid & 31;
    const int row0 = blockIdx.x * TILE_M;
    const uint32_t sbase = smem_u32(smem);

    if (tid < TILE_M) {
        int r = row0 + tid;
        dinv_sh[tid] = (r < V) ? rsqrtf(1.0f + (float)g_cnt[r]) : 0.0f;
    }

    {
        const uint4* s1 = reinterpret_cast<const uint4*>(g_w1);
        const uint4* s2 = reinterpret_cast<const uint4*>(g_w2);
#pragma unroll
        for (int i = 0; i < 8; i++) {
            int idx = tid + i * 256;
            int r = idx >> 4;
            int c = idx & 15;
            reinterpret_cast<uint4*>(w1 + r * SH)[c] = s1[idx];
            reinterpret_cast<uint4*>(w2 + r * SH)[c] = s2[idx];
        }
    }
    {
        const float4* X4 = reinterpret_cast<const float4*>(X);
#pragma unroll
        for (int i = 0; i < 8; i++) {
            int idx = tid + i * 256;
            int r = idx >> 5;
            int c4 = idx & 31;
            float4 v = make_float4(0.f, 0.f, 0.f, 0.f);
            if (row0 + r < V) v = X4[(size_t)(row0 + r) * 32 + c4];
            __nv_bfloat16 h0 = __float2bfloat16(v.x);
            __nv_bfloat16 h1 = __float2bfloat16(v.y);
            __nv_bfloat16 h2 = __float2bfloat16(v.z);
            __nv_bfloat16 h3 = __float2bfloat16(v.w);
            __nv_bfloat16 l0 = __float2bfloat16(v.x - __bfloat162float(h0));
            __nv_bfloat16 l1 = __float2bfloat16(v.y - __bfloat162float(h1));
            __nv_bfloat16 l2 = __float2bfloat16(v.z - __bfloat162float(h2));
            __nv_bfloat16 l3 = __float2bfloat16(v.w - __bfloat162float(h3));
            uint2 hp = make_uint2(pack_bf2(h0, h1), pack_bf2(h2, h3));
            uint2 lp = make_uint2(pack_bf2(l0, l1), pack_bf2(l2, l3));
            *reinterpret_cast<uint2*>(x1 + r * SH + c4 * 4) = hp;
            *reinterpret_cast<uint2*>(x2 + r * SH + c4 * 4) = lp;
        }
    }
    __syncthreads();

    const int wr = (wid & 1) * 32;
    const int wc = (wid >> 1) * 32;
    const int g = lane >> 2;
    const int tg = lane & 3;

    const uint32_t a_row = (uint32_t)((wr + (lane & 15)) * SH + (lane >> 4) * 8) * 2;
    const uint32_t aoff_mt = 16 * SH * 2;
    uint32_t b_row[2];
#pragma unroll
    for (int p = 0; p < 2; p++)
        b_row[p] = (uint32_t)((wc + (2 * p + (lane >> 4)) * 8 + (lane & 7)) * SH +
                              ((lane >> 3) & 1) * 8) * 2;

    float acc[2][4][4];
#pragma unroll
    for (int mt = 0; mt < 2; mt++)
#pragma unroll
        for (int nt = 0; nt < 4; nt++)
#pragma unroll
            for (int j = 0; j < 4; j++) acc[mt][nt][j] = 0.0f;

#pragma unroll
    for (int kb = 0; kb < DIM; kb += 16) {
        const uint32_t koff = (uint32_t)kb * 2;
        uint32_t ah[2][4], al[2][4];
#pragma unroll
        for (int mt = 0; mt < 2; mt++) {
            LDSM_X4(ah[mt][0], ah[mt][1], ah[mt][2], ah[mt][3],
                    sbase + X1_OFF + a_row + mt * aoff_mt + koff);
            LDSM_X4(al[mt][0], al[mt][1], al[mt][2], al[mt][3],
                    sbase + X2_OFF + a_row + mt * aoff_mt + koff);
        }
        uint32_t bh0[4], bh1[4], bl0[4], bl1[4];
#pragma unroll
        for (int p = 0; p < 2; p++) {
            LDSM_X4(bh0[2 * p], bh1[2 * p], bh0[2 * p + 1], bh1[2 * p + 1],
                    sbase + W1_OFF + b_row[p] + koff);
            LDSM_X4(bl0[2 * p], bl1[2 * p], bl0[2 * p + 1], bl1[2 * p + 1],
                    sbase + W2_OFF + b_row[p] + koff);
        }
#pragma unroll
        for (int nt = 0; nt < 4; nt++)
#pragma unroll
            for (int mt = 0; mt < 2; mt++) {
                MMA_BF16(acc[mt][nt], ah[mt], bh0[nt], bh1[nt]);
                MMA_BF16(acc[mt][nt], ah[mt], bl0[nt], bl1[nt]);
                MMA_BF16(acc[mt][nt], al[mt], bh0[nt], bh1[nt]);
            }
    }
    __syncthreads();

    {
        float* stage = reinterpret_cast<float*>(smem);
#pragma unroll
        for (int mt = 0; mt < 2; mt++) {
#pragma unroll
            for (int nt = 0; nt < 4; nt++) {
                int rs = wr + mt * 16 + g;
                int cs = wc + nt * 8 + 2 * tg;
                stage[rs * STAGE_STRIDE + cs]           = acc[mt][nt][0];
                stage[rs * STAGE_STRIDE + cs + 1]       = acc[mt][nt][1];
                stage[(rs + 8) * STAGE_STRIDE + cs]     = acc[mt][nt][2];
                stage[(rs + 8) * STAGE_STRIDE + cs + 1] = acc[mt][nt][3];
            }
        }
    }
    __syncthreads();

    // Coalesced fp16 store: g_h_h = fp16(dinv * D)
    {
        const float* stage = reinterpret_cast<const float*>(smem);
#pragma unroll
        for (int i = 0; i < 8; i++) {
            int idx = tid + i * 256;
            int m = idx >> 5;
            int c4 = idx & 31;
            int row = row0 + m;
            if (row < V) {
                const float4 v = *reinterpret_cast<const float4*>(
                    stage + m * STAGE_STRIDE + c4 * 4);
                float s = dinv_sh[m];
                __half2 p0 = __floats2half2_rn(v.x * s, v.y * s);
                __half2 p1 = __floats2half2_rn(v.z * s, v.w * s);
                uint2 hp = make_uint2(*reinterpret_cast<uint32_t*>(&p0),
                                      *reinterpret_cast<uint32_t*>(&p1));
                reinterpret_cast<uint2*>(g_h_h)[(size_t)row * 32 + c4] = hp;
            }
        }
    }
}

// ---------------------------------------------------------------------------
// gather aggregation: warp per node v.  (fp16 g_h rows, fp32 accumulate)
// nodes[v] = rsqrt(1+cnt)*( h[v] + sum_src h[src] ) + bias
// ---------------------------------------------------------------------------
__global__ void __launch_bounds__(256) k_gather(const float* __restrict__ bias, int V) {
    int v = (blockIdx.x * blockDim.x + threadIdx.x) >> 5;
    int lane = threadIdx.x & 31;
    if (v >= V) return;

    int cnt_raw = g_cnt[v];
    int cnt = cnt_raw > CAP ? CAP : cnt_raw;

    const uint2* H = reinterpret_cast<const uint2*>(g_h_h);
    auto unp = [](uint2 hv, float4& f) {
        float2 a = __half22float2(*reinterpret_cast<__half2*>(&hv.x));
        float2 b = __half22float2(*reinterpret_cast<__half2*>(&hv.y));
        f.x = a.x; f.y = a.y; f.z = b.x; f.w = b.y;
    };

    float4 s0, s1 = make_float4(0.f, 0.f, 0.f, 0.f);
    unp(H[(size_t)v * 32 + lane], s0);       // self-loop term h[v]
    const int* adj = g_adj + (size_t)v * CAP;

    for (int base = 0; base < cnt; base += 32) {
        int n = cnt - base;
        if (n > 32) n = 32;
        int src = (lane < n) ? __ldg(adj + base + lane) : 0;
        int i = 0;
        for (; i + 1 < n; i += 2) {
            int sj0 = __shfl_sync(0xffffffffu, src, i);
            int sj1 = __shfl_sync(0xffffffffu, src, i + 1);
            float4 a, b;
            unp(H[(size_t)sj0 * 32 + lane], a);
            unp(H[(size_t)sj1 * 32 + lane], b);
            s0.x += a.x; s0.y += a.y; s0.z += a.z; s0.w += a.w;
            s1.x += b.x; s1.y += b.y; s1.z += b.z; s1.w += b.w;
        }
        if (i < n) {
            int sj = __shfl_sync(0xffffffffu, src, i);
            float4 a;
            unp(H[(size_t)sj * 32 + lane], a);
            s0.x += a.x; s0.y += a.y; s0.z += a.z; s0.w += a.w;
        }
    }

    float dv = rsqrtf(1.0f + (float)cnt_raw);
    const float4 bv = reinterpret_cast<const float4*>(bias)[lane];
    float4 r = make_float4(fmaf(dv, s0.x + s1.x, bv.x),
                           fmaf(dv, s0.y + s1.y, bv.y),
                           fmaf(dv, s0.z + s1.z, bv.z),
                           fmaf(dv, s0.w + s1.w, bv.w));
    reinterpret_cast<float4*>(g_nodes)[(size_t)v * 32 + lane] = r;
    __half2 h01 = __floats2half2_rn(r.x, r.y);
    __half2 h23 = __floats2half2_rn(r.z, r.w);
    uint2 hp = make_uint2(*reinterpret_cast<uint32_t*>(&h01),
                          *reinterpret_cast<uint32_t*>(&h23));
    reinterpret_cast<uint2*>(g_nodes_h)[(size_t)v * 32 + lane] = hp;
}

// ---------------------------------------------------------------------------
// scoring: block = one item; 4 warps x 16 samples.
// item row fp32 (bias folded), sample rows fp16.
// ---------------------------------------------------------------------------
__global__ void __launch_bounds__(128) k_scores(const int* __restrict__ items,
                                                const int* __restrict__ samples,
                                                float* __restrict__ out, int S) {
    __shared__ float item_sh[DIM];
    const int b = blockIdx.x;
    const int t = threadIdx.x;

    const int item = __ldg(items + b);
    item_sh[t] = g_nodes[(size_t)item * DIM + t];
    __syncthreads();

    const int warp = t >> 5;
    const int lane = t & 31;
    const float4 iv = reinterpret_cast<const float4*>(item_sh)[lane];

    const int* samp = samples + (size_t)b * S;
    const uint2* NH = reinterpret_cast<const uint2*>(g_nodes_h);
#pragma unroll 4
    for (int i = 0; i < 16; i++) {
        int s = warp * 16 + i;
        int sidx = __ldg(samp + s);
        uint2 hv = NH[(size_t)sidx * 32 + lane];
        float2 f0 = __half22float2(*reinterpret_cast<__half2*>(&hv.x));
        float2 f1 = __half22float2(*reinterpret_cast<__half2*>(&hv.y));
        float p = iv.x * f0.x + iv.y * f0.y + iv.z * f1.x + iv.w * f1.y;
#pragma unroll
        for (int off = 16; off > 0; off >>= 1)
            p += __shfl_xor_sync(0xffffffffu, p, off);
        if (lane == 0) out[(size_t)b * S + s] = p;
    }
}

// ---------------------------------------------------------------------------
// launcher
// ---------------------------------------------------------------------------
extern "C" void kernel_launch(void* const* d_in, const int* in_sizes, int n_in,
                              void* d_out, int out_size) {
    const int*   items   = (const int*)d_in[0];
    const int*   samples = (const int*)d_in[1];
    const int*   edge    = (const int*)d_in[2];
    const float* emb     = (const float*)d_in[3];
    const float* W       = (const float*)d_in[4];
    const float* bias    = (const float*)d_in[5];
    float*       out     = (float*)d_out;

    const int B = in_sizes[0];
    const int S = in_sizes[1] / B;
    const int E = in_sizes[2] / 2;
    const int V = in_sizes[3] / DIM;

    // prep (zero counts + W split), adjacency build
    k_prep<<<(V + 255) / 256, 256>>>(W, V);
    k_fill<<<(E + 255) / 256, 256>>>(edge, E);

    // tensor-core GEMM (ldmatrix + mma.sync), writes fp16 g_h
    cudaFuncSetAttribute(k_gemm, cudaFuncAttributeMaxDynamicSharedMemorySize, GEMM_SMEM);
    k_gemm<<<(V + TILE_M - 1) / TILE_M, 256, GEMM_SMEM>>>(emb, V);

    // gather aggregation (warp per node) -> g_nodes (+bias) and fp16 copy
    k_gather<<<(V + 7) / 8, 256>>>(bias, V);

    // scoring (fp16 sample rows)
    k_scores<<<B, 128>>>(items, samples, out, S);
}